// round 13
// baseline (speedup 1.0000x reference)
#include <cuda_runtime.h>
#include <cuda_bf16.h>
#include <mma.h>
#include <cstdint>
#include <math.h>

using namespace nvcuda;

#define B_    16
#define C_    3
#define H_    64
#define W_    64
#define P_    256
#define PS_   9
#define E_    256
#define NH_   8
#define DH_   32
#define HW_   4096
#define POSD_ 64
#define BP_   (B_*P_)               // 4096
#define NPATCH (B_*P_*C_*PS_*PS_)   // 995328
#define NPOS   (BP_*POSD_)          // 262144
#define QKVN  768
#define KC_   256                   // conv GEMM K (243 padded)

// ---------------- scratch ----------------
__device__ __nv_bfloat16 g_wH [E_*KC_];
__device__ __nv_bfloat16 g_wL [E_*KC_];
__device__ __nv_bfloat16 g_featH[(size_t)BP_*HW_];
__device__ __nv_bfloat16 g_featL[(size_t)BP_*HW_];
__device__ __nv_bfloat16 g_inwTh[(size_t)E_*HW_];
__device__ __nv_bfloat16 g_inwTl[(size_t)E_*HW_];
__device__ __nv_bfloat16 g_qkvwTh[QKVN*E_];
__device__ __nv_bfloat16 g_qkvwTl[QKVN*E_];
__device__ float g_qkvb[QKVN];
__device__ float g_part[4*(size_t)BP_*E_];
__device__ __nv_bfloat16 g_tokH[BP_*E_];
__device__ __nv_bfloat16 g_tokL[BP_*E_];
__device__ __nv_bfloat16 g_qkvH[(size_t)BP_*QKVN];
__device__ __nv_bfloat16 g_qkvL[(size_t)BP_*QKVN];
__device__ float g_o  [BP_*E_];
__device__ float g_Mf [E_*2];
__device__ float g_cf [2];
__device__ float g_Mfo[E_*2];
__device__ float g_cfo[2];
__device__ float g_tp [BP_*2];

// ---------------- cp.async helpers ----------------
__device__ __forceinline__ uint32_t smem_u32(const void* p) {
    uint32_t a;
    asm("{ .reg .u64 t; cvta.to.shared.u64 t, %1; cvt.u32.u64 %0, t; }" : "=r"(a) : "l"(p));
    return a;
}
#define CP_ASYNC16(dst, src) \
    asm volatile("cp.async.cg.shared.global [%0], [%1], 16;" :: "r"(dst), "l"(src))
#define CP_COMMIT() asm volatile("cp.async.commit_group;" ::: "memory")
#define CP_WAIT0()  asm volatile("cp.async.wait_group 0;" ::: "memory")

__device__ __forceinline__ uint2 pack4_bf16(float a, float b, float c, float d) {
    __nv_bfloat162 lo = __floats2bfloat162_rn(a, b);
    __nv_bfloat162 hi = __floats2bfloat162_rn(c, d);
    uint2 r;
    r.x = *(uint32_t*)&lo;
    r.y = *(uint32_t*)&hi;
    return r;
}

// =====================================================================
// prep_small: wprep (0..255) + concat_bias (256..258) + fold1 (259..515)
// =====================================================================
__global__ void prep_small_kernel(const float* __restrict__ conv_w,
                                  __nv_bfloat16* __restrict__ wH,
                                  __nv_bfloat16* __restrict__ wL,
                                  const float* __restrict__ bq,
                                  const float* __restrict__ bk,
                                  const float* __restrict__ bv,
                                  float* __restrict__ qkvb,
                                  const float* __restrict__ out_w,
                                  const float* __restrict__ out_b,
                                  const float* __restrict__ fc_w,
                                  const float* __restrict__ fc_b,
                                  float* __restrict__ Mf,
                                  float* __restrict__ cf) {
    const int bid = blockIdx.x, tid = threadIdx.x;
    if (bid < 256) {
        int idx = bid*256 + tid;
        int oc = idx >> 8, k = idx & 255;
        float v = (k < 243) ? conv_w[oc*243 + k] : 0.f;
        __nv_bfloat16 h = __float2bfloat16(v);
        wH[idx] = h;
        wL[idx] = __float2bfloat16(v - __bfloat162float(h));
        return;
    }
    if (bid < 259) {
        int i = (bid - 256)*256 + tid;
        if (i < 768) qkvb[i] = (i < 256) ? bq[i] : (i < 512 ? bk[i-256] : bv[i-512]);
        return;
    }
    const int e = bid - 259;
    const float* arow = (e < E_) ? (out_w + (size_t)e*HW_) : out_b;
    float s0 = 0.f, s1 = 0.f;
    for (int i = tid; i < HW_; i += 256) {
        float a = arow[i];
        float2 f = *(const float2*)&fc_w[i*2];
        s0 = fmaf(a, f.x, s0);
        s1 = fmaf(a, f.y, s1);
    }
    __shared__ float red0[8], red1[8];
    const int lane = tid & 31, warp = tid >> 5;
#pragma unroll
    for (int o = 16; o; o >>= 1) {
        s0 += __shfl_xor_sync(0xffffffffu, s0, o);
        s1 += __shfl_xor_sync(0xffffffffu, s1, o);
    }
    if (lane == 0) { red0[warp] = s0; red1[warp] = s1; }
    __syncthreads();
    if (tid == 0) {
        float t0 = 0.f, t1 = 0.f;
#pragma unroll
        for (int i = 0; i < 8; i++) { t0 += red0[i]; t1 += red1[i]; }
        if (e < E_) { Mf[e*2] = t0; Mf[e*2+1] = t1; }
        else        { cf[0] = t0 + fc_b[0]; cf[1] = t1 + fc_b[1]; }
    }
}

// =====================================================================
// Batched transpose + bf16 split
// =====================================================================
__global__ void transpose_all_kernel(const float* __restrict__ in_w,
                                     const float* __restrict__ wq,
                                     const float* __restrict__ wk,
                                     const float* __restrict__ wv,
                                     __nv_bfloat16* __restrict__ inwTh,
                                     __nv_bfloat16* __restrict__ inwTl,
                                     __nv_bfloat16* __restrict__ qkvwTh,
                                     __nv_bfloat16* __restrict__ qkvwTl) {
    __shared__ float tile[32][33];
    const int y = blockIdx.y;
    const float* src; int Kd, k0;
    __nv_bfloat16 *oH, *oL;
    if (y < 128) {
        src = in_w; Kd = HW_; k0 = y << 5; oH = inwTh; oL = inwTl;
    } else {
        int g  = (y - 128) >> 3;
        int yy = (y - 128) & 7;
        src = (g == 0) ? wq : (g == 1) ? wk : wv;
        Kd = E_; k0 = yy << 5;
        oH = qkvwTh + g*256*E_; oL = qkvwTl + g*256*E_;
    }
    const int n0 = blockIdx.x << 5;
    const int tx = threadIdx.x, ty = threadIdx.y;
    for (int i = ty; i < 32; i += 8)
        tile[i][tx] = src[(size_t)(k0 + i)*E_ + n0 + tx];
    __syncthreads();
    for (int i = ty; i < 32; i += 8) {
        float v = tile[tx][i];
        __nv_bfloat16 h = __float2bfloat16(v);
        size_t o = (size_t)(n0 + i)*Kd + k0 + tx;
        oH[o] = h;
        oL[o] = __float2bfloat16(v - __bfloat162float(h));
    }
}

// =====================================================================
// Shared GEMM geometry
// =====================================================================
#define LDS_  40
#define TILE_B (128*LDS_*2)
#define STAGE_B (4*TILE_B)
#define GEMM_SMEM (2*STAGE_B)        // 81920 B

// =====================================================================
// Fused conv GEMM: feat = relu(W @ im2col(x) + bias), bf16 hi/lo out.
// A = W (cp.async), B = im2col computed on the fly from x (STS).
// grid (32 pixTiles, 2 ocTiles, 16 batch), 8 warps, 2 CTAs/SM.
// =====================================================================
__global__ __launch_bounds__(256, 2)
void conv_gemm_kernel(const __nv_bfloat16* __restrict__ wH,
                      const __nv_bfloat16* __restrict__ wL,
                      const float* __restrict__ x,
                      const float* __restrict__ bias,
                      __nv_bfloat16* __restrict__ CH,
                      __nv_bfloat16* __restrict__ CL) {
    extern __shared__ char smem[];
    __shared__ int lut[256];
    const int tid = threadIdx.x;
    const int wid = tid >> 5;
    const int warpM = wid & 1;
    const int warpN = wid >> 1;
    const int mBase = blockIdx.y << 7;     // oc
    const int nBase = blockIdx.x << 7;     // pix
    const int b = blockIdx.z;
    const float* xb = x + ((size_t)b*3 << 12);

    if (tid < 256) {
        int k = tid;
        int c = k / 81, r = k - c*81, ky = r / 9, kx = r - ky*9;
        lut[k] = (k < 243) ? ((c << 8) | (ky << 4) | kx) : -1;
    }

    const uint32_t smemBase = smem_u32(smem);
    const __nv_bfloat16* aSrc[2] = { wH + (size_t)mBase*KC_, wL + (size_t)mBase*KC_ };

    auto load_A = [&](int s, int kg) {
        const uint32_t sb = smemBase + s*STAGE_B;
#pragma unroll
        for (int t = 0; t < 2; t++) {
            const __nv_bfloat16* src = aSrc[t];
            const uint32_t dst = sb + t*TILE_B;
#pragma unroll
            for (int i = 0; i < 2; i++) {
                int idx = tid + (i << 8);
                int row = idx >> 2, seg = idx & 3;
                CP_ASYNC16(dst + (uint32_t)(row*(LDS_*2) + seg*16),
                           (const char*)(src + (size_t)row*KC_ + kg + seg*8));
            }
        }
    };

    // compute im2col B tile (128 pix x 32 k) for chunk kc into stage s
    auto load_B = [&](int s, int kc) {
        __nv_bfloat16* Bh = (__nv_bfloat16*)(smem + s*STAGE_B + 2*TILE_B);
        __nv_bfloat16* Bl = Bh + 128*LDS_;
#pragma unroll
        for (int i = 0; i < 4; i++) {
            int item = tid + (i << 8);           // 0..1023
            int row = item >> 3;                 // pix row in tile
            int g   = item & 7;                  // group of 4 k
            int pix = nBase + row;
            int py = pix >> 6, px = pix & 63;
            float vh[4], vl[4];
#pragma unroll
            for (int u = 0; u < 4; u++) {
                int k = (kc << 5) + (g << 2) + u;
                int L = lut[k];
                float v = 0.f;
                if (L >= 0) {
                    int c = L >> 8, ky = (L >> 4) & 15, kx = L & 15;
                    int yy = py + ky - 4;
                    int xx = px + kx - 4;
                    if (yy >= 0 && yy < 64 && xx >= 0 && xx < 64)
                        v = xb[(c << 12) + (yy << 6) + xx];
                }
                float h = __bfloat162float(__float2bfloat16(v));
                vh[u] = v;
                vl[u] = v - h;
            }
            const int off = row*LDS_ + (g << 2);
            *(uint2*)(Bh + off) = pack4_bf16(vh[0], vh[1], vh[2], vh[3]);
            *(uint2*)(Bl + off) = pack4_bf16(vl[0], vl[1], vl[2], vl[3]);
        }
    };

    wmma::fragment<wmma::accumulator, 16,16,16, float> acc[4][2];
#pragma unroll
    for (int i = 0; i < 4; i++)
#pragma unroll
        for (int j = 0; j < 2; j++) wmma::fill_fragment(acc[i][j], 0.f);

    load_A(0, 0); CP_COMMIT();
    __syncthreads();           // lut ready
    load_B(0, 0);

    const int nChunks = KC_ >> 5;   // 8
    for (int c = 0; c < nChunks; c++) {
        CP_WAIT0();
        __syncthreads();            // stage c fully resident; prev MMAs done
        if (c + 1 < nChunks) {
            load_A((c+1) & 1, (c+1) << 5); CP_COMMIT();
            load_B((c+1) & 1, c+1);
        }

        const __nv_bfloat16* As_h = (const __nv_bfloat16*)(smem + (c&1)*STAGE_B);
        const __nv_bfloat16* As_l = As_h + 128*LDS_;
        const __nv_bfloat16* Bs_h = As_l + 128*LDS_;
        const __nv_bfloat16* Bs_l = Bs_h + 128*LDS_;

#pragma unroll
        for (int ks = 0; ks < 2; ks++) {
            wmma::fragment<wmma::matrix_a, 16,16,16, __nv_bfloat16, wmma::row_major> a_h[4], a_l[4];
            wmma::fragment<wmma::matrix_b, 16,16,16, __nv_bfloat16, wmma::col_major> b_h[2], b_l[2];
#pragma unroll
            for (int i = 0; i < 4; i++) {
                const int r = (warpM*64 + i*16)*LDS_ + ks*16;
                wmma::load_matrix_sync(a_h[i], As_h + r, LDS_);
                wmma::load_matrix_sync(a_l[i], As_l + r, LDS_);
            }
#pragma unroll
            for (int j = 0; j < 2; j++) {
                const int r = (warpN*32 + j*16)*LDS_ + ks*16;
                wmma::load_matrix_sync(b_h[j], Bs_h + r, LDS_);
                wmma::load_matrix_sync(b_l[j], Bs_l + r, LDS_);
            }
#pragma unroll
            for (int i = 0; i < 4; i++)
#pragma unroll
                for (int j = 0; j < 2; j++) {
                    wmma::mma_sync(acc[i][j], a_h[i], b_h[j], acc[i][j]);
                    wmma::mma_sync(acc[i][j], a_h[i], b_l[j], acc[i][j]);
                    wmma::mma_sync(acc[i][j], a_l[i], b_h[j], acc[i][j]);
                }
        }
    }

    // epilogue: relu + bias[oc] + bf16 split
    __syncthreads();
    float* sC = (float*)smem;
#pragma unroll
    for (int i = 0; i < 4; i++)
#pragma unroll
        for (int j = 0; j < 2; j++)
            wmma::store_matrix_sync(sC + (size_t)(warpM*64 + i*16)*128 + warpN*32 + j*16,
                                    acc[i][j], 128, wmma::mem_row_major);
    __syncthreads();

#pragma unroll
    for (int t = 0; t < 16; t++) {
        int lin = tid + (t << 8);
        int row = lin >> 5;
        int col = (lin & 31) << 2;
        float4 v = *(const float4*)(sC + row*128 + col);
        const int oc = mBase + row;
        const size_t gm = (size_t)(b*P_ + oc)*HW_ + nBase + col;
        const float bb = bias[oc];
        float r0 = fmaxf(v.x + bb, 0.f), r1 = fmaxf(v.y + bb, 0.f);
        float r2 = fmaxf(v.z + bb, 0.f), r3 = fmaxf(v.w + bb, 0.f);
        float h0 = __bfloat162float(__float2bfloat16(r0));
        float h1 = __bfloat162float(__float2bfloat16(r1));
        float h2 = __bfloat162float(__float2bfloat16(r2));
        float h3 = __bfloat162float(__float2bfloat16(r3));
        *(uint2*)(CH + gm) = pack4_bf16(r0, r1, r2, r3);
        *(uint2*)(CL + gm) = pack4_bf16(r0 - h0, r1 - h1, r2 - h2, r3 - h3);
    }
}

// =====================================================================
// wmma bf16-split GEMM (modes 1, 3).
// =====================================================================
template<int MODE>
__global__ __launch_bounds__(256, 2)
void gemm_wmma(const __nv_bfloat16* __restrict__ Ah, const __nv_bfloat16* __restrict__ Al,
               const __nv_bfloat16* __restrict__ Bh, const __nv_bfloat16* __restrict__ Bl,
               int K, int ldc, int kLen, size_t bOffZ, size_t cOffZ, int kOffZ,
               const float* __restrict__ bias, float* __restrict__ C,
               __nv_bfloat16* __restrict__ CH, __nv_bfloat16* __restrict__ CL) {
    extern __shared__ char smem[];
    const int tid = threadIdx.x;
    const int wid = tid >> 5;
    const int warpM = wid & 1;
    const int warpN = wid >> 1;
    const int mBase = blockIdx.y << 7;
    const int nBase = blockIdx.x << 7;
    const int z = blockIdx.z;

    Bh += (size_t)z * bOffZ;  Bl += (size_t)z * bOffZ;
    if (MODE == 3) { CH += (size_t)z * cOffZ; CL += (size_t)z * cOffZ; }
    else             C += (size_t)z * cOffZ;
    const int k0 = z * kOffZ;

    const __nv_bfloat16* srcs[4] = {
        Ah + (size_t)mBase*K, Al + (size_t)mBase*K,
        Bh + (size_t)nBase*K, Bl + (size_t)nBase*K };

    const uint32_t smemBase = smem_u32(smem);

    auto load_stage = [&](int s, int kg) {
        const uint32_t sb = smemBase + s*STAGE_B;
#pragma unroll
        for (int t = 0; t < 4; t++) {
            const __nv_bfloat16* src = srcs[t];
            const uint32_t dst = sb + t*TILE_B;
#pragma unroll
            for (int i = 0; i < 2; i++) {
                int idx = tid + (i << 8);
                int row = idx >> 2, seg = idx & 3;
                CP_ASYNC16(dst + (uint32_t)(row*(LDS_*2) + seg*16),
                           (const char*)(src + (size_t)row*K + kg + seg*8));
            }
        }
    };

    wmma::fragment<wmma::accumulator, 16,16,16, float> acc[4][2];
#pragma unroll
    for (int i = 0; i < 4; i++)
#pragma unroll
        for (int j = 0; j < 2; j++) wmma::fill_fragment(acc[i][j], 0.f);

    const int nChunks = kLen >> 5;
    load_stage(0, k0); CP_COMMIT();

    for (int c = 0; c < nChunks; c++) {
        CP_WAIT0();
        __syncthreads();
        if (c + 1 < nChunks) { load_stage((c+1) & 1, k0 + ((c+1) << 5)); CP_COMMIT(); }

        const __nv_bfloat16* As_h = (const __nv_bfloat16*)(smem + (c&1)*STAGE_B);
        const __nv_bfloat16* As_l = As_h + 128*LDS_;
        const __nv_bfloat16* Bs_h = As_l + 128*LDS_;
        const __nv_bfloat16* Bs_l = Bs_h + 128*LDS_;

#pragma unroll
        for (int ks = 0; ks < 2; ks++) {
            wmma::fragment<wmma::matrix_a, 16,16,16, __nv_bfloat16, wmma::row_major> a_h[4], a_l[4];
            wmma::fragment<wmma::matrix_b, 16,16,16, __nv_bfloat16, wmma::col_major> b_h[2], b_l[2];
#pragma unroll
            for (int i = 0; i < 4; i++) {
                const int r = (warpM*64 + i*16)*LDS_ + ks*16;
                wmma::load_matrix_sync(a_h[i], As_h + r, LDS_);
                wmma::load_matrix_sync(a_l[i], As_l + r, LDS_);
            }
#pragma unroll
            for (int j = 0; j < 2; j++) {
                const int r = (warpN*32 + j*16)*LDS_ + ks*16;
                wmma::load_matrix_sync(b_h[j], Bs_h + r, LDS_);
                wmma::load_matrix_sync(b_l[j], Bs_l + r, LDS_);
            }
#pragma unroll
            for (int i = 0; i < 4; i++)
#pragma unroll
                for (int j = 0; j < 2; j++) {
                    wmma::mma_sync(acc[i][j], a_h[i], b_h[j], acc[i][j]);
                    wmma::mma_sync(acc[i][j], a_h[i], b_l[j], acc[i][j]);
                    wmma::mma_sync(acc[i][j], a_l[i], b_h[j], acc[i][j]);
                }
        }
    }

    if (MODE == 1) {
#pragma unroll
        for (int i = 0; i < 4; i++)
#pragma unroll
            for (int j = 0; j < 2; j++)
                wmma::store_matrix_sync(
                    C + (size_t)(mBase + warpM*64 + i*16)*ldc + nBase + warpN*32 + j*16,
                    acc[i][j], ldc, wmma::mem_row_major);
        return;
    }

    __syncthreads();
    float* sC = (float*)smem;
#pragma unroll
    for (int i = 0; i < 4; i++)
#pragma unroll
        for (int j = 0; j < 2; j++)
            wmma::store_matrix_sync(sC + (size_t)(warpM*64 + i*16)*128 + warpN*32 + j*16,
                                    acc[i][j], 128, wmma::mem_row_major);
    __syncthreads();

#pragma unroll
    for (int t = 0; t < 16; t++) {
        int lin = tid + (t << 8);
        int row = lin >> 5;
        int col = (lin & 31) << 2;
        float4 v = *(const float4*)(sC + row*128 + col);
        const int gm = mBase + row, gn = nBase + col;
        const float4 bv = *(const float4*)(bias + gn);
        float r0 = v.x + bv.x, r1 = v.y + bv.y, r2 = v.z + bv.z, r3 = v.w + bv.w;
        float h0 = __bfloat162float(__float2bfloat16(r0));
        float h1 = __bfloat162float(__float2bfloat16(r1));
        float h2 = __bfloat162float(__float2bfloat16(r2));
        float h3 = __bfloat162float(__float2bfloat16(r3));
        *(uint2*)(CH + (size_t)gm*ldc + gn) = pack4_bf16(r0, r1, r2, r3);
        *(uint2*)(CL + (size_t)gm*ldc + gn) =
            pack4_bf16(r0 - h0, r1 - h1, r2 - h2, r3 - h3);
    }
}

// reduce split-K partials + bias -> tok bf16 hi/lo (vectorized x4)
__global__ void reduce_tok_kernel(const float* __restrict__ part,
                                  const float* __restrict__ bias,
                                  __nv_bfloat16* __restrict__ tokH,
                                  __nv_bfloat16* __restrict__ tokL) {
    int t = blockIdx.x*256 + threadIdx.x;
    if (t >= (BP_*E_)/4) return;
    const int idx = t << 2;
    const size_t S = (size_t)BP_*E_;
    float4 p0 = *(const float4*)(part + idx);
    float4 p1 = *(const float4*)(part + idx + S);
    float4 p2 = *(const float4*)(part + idx + 2*S);
    float4 p3 = *(const float4*)(part + idx + 3*S);
    float4 bv = *(const float4*)(bias + (idx & 255));
    float v0 = p0.x + p1.x + p2.x + p3.x + bv.x;
    float v1 = p0.y + p1.y + p2.y + p3.y + bv.y;
    float v2 = p0.z + p1.z + p2.z + p3.z + bv.z;
    float v3 = p0.w + p1.w + p2.w + p3.w + bv.w;
    float h0 = __bfloat162float(__float2bfloat16(v0));
    float h1 = __bfloat162float(__float2bfloat16(v1));
    float h2 = __bfloat162float(__float2bfloat16(v2));
    float h3 = __bfloat162float(__float2bfloat16(v3));
    *(uint2*)(tokH + idx) = pack4_bf16(v0, v1, v2, v3);
    *(uint2*)(tokL + idx) = pack4_bf16(v0 - h0, v1 - h1, v2 - h2, v3 - h3);
}

// =====================================================================
// Tensor-core attention (R12 proven)
// =====================================================================
#define ASLD 264
#define ATT_SMEM (64*ASLD*4 + 2*(64*ASLD*2) + 2*(64*40*2) + 4*(256*40*2))  // 227328 B

__global__ __launch_bounds__(256)
void attn_wmma_kernel(const __nv_bfloat16* __restrict__ qkvH,
                      const __nv_bfloat16* __restrict__ qkvL,
                      float* __restrict__ o) {
    extern __shared__ char sm_[];
    float*        sS  = (float*)sm_;
    __nv_bfloat16* sPh = (__nv_bfloat16*)(sS + 64*ASLD);
    __nv_bfloat16* sPl = sPh + 64*ASLD;
    __nv_bfloat16* sQh = sPl + 64*ASLD;
    __nv_bfloat16* sQl = sQh + 64*40;
    __nv_bfloat16* sKh = sQl + 64*40;
    __nv_bfloat16* sKl = sKh + 256*40;
    __nv_bfloat16* sVh = sKl + 256*40;
    __nv_bfloat16* sVl = sVh + 256*40;

    const int bh = blockIdx.y, b = bh >> 3, h = bh & 7;
    const int q0 = blockIdx.x << 6;
    const int tid = threadIdx.x;
    const int wid = tid >> 5;
    const float scale = 0.17677669529663687f;

    const size_t rowQ = (size_t)(b*P_ + q0)*QKVN + h*32;
    const size_t rowK = (size_t)(b*P_)*QKVN + 256 + h*32;
    const size_t rowV = (size_t)(b*P_)*QKVN + 512 + h*32;
    for (int i = tid; i < 512; i += 256) {
        int a = i >> 8, r = (i >> 2) & 63, s = i & 3;
        const __nv_bfloat16* src = (a ? qkvL : qkvH) + rowQ + (size_t)r*QKVN + s*8;
        *(uint4*)((a ? sQl : sQh) + r*40 + s*8) = *(const uint4*)src;
    }
    for (int i = tid; i < 2048; i += 256) {
        int a = i >> 10, r = (i >> 2) & 255, s = i & 3;
        const __nv_bfloat16* srck = (a ? qkvL : qkvH) + rowK + (size_t)r*QKVN + s*8;
        *(uint4*)((a ? sKl : sKh) + r*40 + s*8) = *(const uint4*)srck;
        const __nv_bfloat16* srcv = (a ? qkvL : qkvH) + rowV + (size_t)r*QKVN + s*8;
        *(uint4*)((a ? sVl : sVh) + r*40 + s*8) = *(const uint4*)srcv;
    }
    __syncthreads();

    {
        const int wm = wid & 1, wn = wid >> 1;
        wmma::fragment<wmma::accumulator, 16,16,16, float> acc[2][4];
#pragma unroll
        for (int i = 0; i < 2; i++)
#pragma unroll
            for (int j = 0; j < 4; j++) wmma::fill_fragment(acc[i][j], 0.f);
#pragma unroll
        for (int ks = 0; ks < 2; ks++) {
            wmma::fragment<wmma::matrix_a, 16,16,16, __nv_bfloat16, wmma::row_major> a_h[2], a_l[2];
            wmma::fragment<wmma::matrix_b, 16,16,16, __nv_bfloat16, wmma::col_major> b_h[4], b_l[4];
#pragma unroll
            for (int i = 0; i < 2; i++) {
                const int r = (wm*32 + i*16)*40 + ks*16;
                wmma::load_matrix_sync(a_h[i], sQh + r, 40);
                wmma::load_matrix_sync(a_l[i], sQl + r, 40);
            }
#pragma unroll
            for (int j = 0; j < 4; j++) {
                const int r = (wn*64 + j*16)*40 + ks*16;
                wmma::load_matrix_sync(b_h[j], sKh + r, 40);
                wmma::load_matrix_sync(b_l[j], sKl + r, 40);
            }
#pragma unroll
            for (int i = 0; i < 2; i++)
#pragma unroll
                for (int j = 0; j < 4; j++) {
                    wmma::mma_sync(acc[i][j], a_h[i], b_h[j], acc[i][j]);
                    wmma::mma_sync(acc[i][j], a_h[i], b_l[j], acc[i][j]);
                    wmma::mma_sync(acc[i][j], a_l[i], b_h[j], acc[i][j]);
                }
        }
#pragma unroll
        for (int i = 0; i < 2; i++)
#pragma unroll
            for (int j = 0; j < 4; j++)
                wmma::store_matrix_sync(sS + (wm*32 + i*16)*ASLD + wn*64 + j*16,
                                        acc[i][j], ASLD, wmma::mem_row_major);
    }
    __syncthreads();

    {
        const int warp = wid, lane = tid & 31;
        for (int r = warp; r < 64; r += 8) {
            float4* row = (float4*)(sS + r*ASLD);
            float4 v0 = row[lane], v1 = row[lane + 32];
            v0.x *= scale; v0.y *= scale; v0.z *= scale; v0.w *= scale;
            v1.x *= scale; v1.y *= scale; v1.z *= scale; v1.w *= scale;
            float m = fmaxf(fmaxf(fmaxf(v0.x,v0.y), fmaxf(v0.z,v0.w)),
                            fmaxf(fmaxf(v1.x,v1.y), fmaxf(v1.z,v1.w)));
#pragma unroll
            for (int off = 16; off; off >>= 1) m = fmaxf(m, __shfl_xor_sync(0xffffffffu, m, off));
            v0.x = __expf(v0.x-m); v0.y = __expf(v0.y-m); v0.z = __expf(v0.z-m); v0.w = __expf(v0.w-m);
            v1.x = __expf(v1.x-m); v1.y = __expf(v1.y-m); v1.z = __expf(v1.z-m); v1.w = __expf(v1.w-m);
            float s = v0.x+v0.y+v0.z+v0.w + v1.x+v1.y+v1.z+v1.w;
#pragma unroll
            for (int off = 16; off; off >>= 1) s += __shfl_xor_sync(0xffffffffu, s, off);
            const float inv = 1.f / s;
            v0.x*=inv; v0.y*=inv; v0.z*=inv; v0.w*=inv;
            v1.x*=inv; v1.y*=inv; v1.z*=inv; v1.w*=inv;
            row[lane] = v0; row[lane+32] = v1;
        }
    }
    __syncthreads();

    for (int i = tid; i < 4096; i += 256) {
        int r = i >> 6, g = (i & 63) << 2;
        float4 v = *(const float4*)(sS + r*ASLD + g);
        float h0 = __bfloat162float(__float2bfloat16(v.x));
        float h1 = __bfloat162float(__float2bfloat16(v.y));
        float h2 = __bfloat162float(__float2bfloat16(v.z));
        float h3 = __bfloat162float(__float2bfloat16(v.w));
        *(uint2*)(sPh + r*ASLD + g) = pack4_bf16(v.x, v.y, v.z, v.w);
        *(uint2*)(sPl + r*ASLD + g) = pack4_bf16(v.x - h0, v.y - h1, v.z - h2, v.w - h3);
    }
    __syncthreads();

    {
        const int wm = wid & 3, wn = wid >> 2;
        wmma::fragment<wmma::accumulator, 16,16,16, float> acc;
        wmma::fill_fragment(acc, 0.f);
#pragma unroll
        for (int k = 0; k < 16; k++) {
            wmma::fragment<wmma::matrix_a, 16,16,16, __nv_bfloat16, wmma::row_major> a_h, a_l;
            wmma::fragment<wmma::matrix_b, 16,16,16, __nv_bfloat16, wmma::row_major> b_h, b_l;
            wmma::load_matrix_sync(a_h, sPh + (wm*16)*ASLD + k*16, ASLD);
            wmma::load_matrix_sync(a_l, sPl + (wm*16)*ASLD + k*16, ASLD);
            wmma::load_matrix_sync(b_h, sVh + (k*16)*40 + wn*16, 40);
            wmma::load_matrix_sync(b_l, sVl + (k*16)*40 + wn*16, 40);
            wmma::mma_sync(acc, a_h, b_h, acc);
            wmma::mma_sync(acc, a_h, b_l, acc);
            wmma::mma_sync(acc, a_l, b_h, acc);
        }
        wmma::store_matrix_sync(o + (size_t)(b*P_ + q0 + wm*16)*E_ + h*32 + wn*16,
                                acc, E_, wmma::mem_row_major);
    }
}

// =====================================================================
// fold2 + tail
// =====================================================================
__global__ void fold_kernel(const float* __restrict__ Wm,
                            const float* __restrict__ brow,
                            const float* __restrict__ M2,
                            const float* __restrict__ addc,
                            float* __restrict__ outM,
                            float* __restrict__ outc, int L, int R) {
    const int e = blockIdx.x, tid = threadIdx.x;
    const float* arow = (e < R) ? (Wm + (size_t)e*L) : brow;
    float s0 = 0.f, s1 = 0.f;
    for (int i = tid; i < L; i += 256) {
        float a = arow[i];
        float2 f = *(const float2*)&M2[i*2];
        s0 = fmaf(a, f.x, s0);
        s1 = fmaf(a, f.y, s1);
    }
    __shared__ float red0[8], red1[8];
    const int lane = tid & 31, warp = tid >> 5;
#pragma unroll
    for (int o = 16; o; o >>= 1) {
        s0 += __shfl_xor_sync(0xffffffffu, s0, o);
        s1 += __shfl_xor_sync(0xffffffffu, s1, o);
    }
    if (lane == 0) { red0[warp] = s0; red1[warp] = s1; }
    __syncthreads();
    if (tid == 0) {
        float t0 = 0.f, t1 = 0.f;
#pragma unroll
        for (int i = 0; i < 8; i++) { t0 += red0[i]; t1 += red1[i]; }
        if (e < R) { outM[e*2] = t0; outM[e*2+1] = t1; }
        else {
            float c0 = addc ? addc[0] : 0.f, c1 = addc ? addc[1] : 0.f;
            outc[0] = t0 + c0; outc[1] = t1 + c1;
        }
    }
}

__global__ void tp_kernel(const float* __restrict__ o,
                          const float* __restrict__ Mfo,
                          const float* __restrict__ cfo,
                          float* __restrict__ tp) {
    const int row  = (blockIdx.x << 2) + (threadIdx.x >> 5);
    const int lane = threadIdx.x & 31;
    float s0 = 0.f, s1 = 0.f;
#pragma unroll
    for (int t = 0; t < 8; t++) {
        int e = lane + (t << 5);
        float a = o[(size_t)row*E_ + e];
        float2 m = *(const float2*)&Mfo[e*2];
        s0 = fmaf(a, m.x, s0);
        s1 = fmaf(a, m.y, s1);
    }
#pragma unroll
    for (int off = 16; off; off >>= 1) {
        s0 += __shfl_xor_sync(0xffffffffu, s0, off);
        s1 += __shfl_xor_sync(0xffffffffu, s1, off);
    }
    if (lane == 0) {
        tp[row*2+0] = tanhf(s0 + cfo[0]);
        tp[row*2+1] = tanhf(s1 + cfo[1]);
    }
}

__global__ void outputs_kernel(const float* __restrict__ x,
                               const float* __restrict__ tp,
                               const float* __restrict__ pos_w,
                               const float* __restrict__ pos_b,
                               float* __restrict__ out) {
    int idx = blockIdx.x * blockDim.x + threadIdx.x;
    if (idx < NPATCH) {
        const int pix = idx % 81;
        const int c   = (idx / 81) % 3;
        const int bp  = idx / 243;
        const int iy  = pix / 9, ix = pix % 9;
        const int b   = bp >> 8;

        const float tx = tp[bp*2], ty = tp[bp*2+1];
        const float bx = (2.f*ix + 1.f) / 9.f - 1.f;
        const float by = (2.f*iy + 1.f) / 9.f - 1.f;
        const float gx = 0.140625f * bx + tx;
        const float gy = 0.140625f * by + ty;
        const float ixf = ((gx + 1.f) * 64.f - 1.f) * 0.5f;
        const float iyf = ((gy + 1.f) * 64.f - 1.f) * 0.5f;
        const float x0 = floorf(ixf), y0 = floorf(iyf);
        const float wx = ixf - x0,   wy = iyf - y0;
        const int x0i = min(max((int)x0, 0), 63);
        const int x1i = min(max((int)x0 + 1, 0), 63);
        const int y0i = min(max((int)y0, 0), 63);
        const int y1i = min(max((int)y0 + 1, 0), 63);
        const float* img = x + (size_t)(b*3 + c) * 4096;
        const float v00 = img[y0i*64 + x0i], v01 = img[y0i*64 + x1i];
        const float v10 = img[y1i*64 + x0i], v11 = img[y1i*64 + x1i];
        out[idx] = v00*(1.f-wx)*(1.f-wy) + v01*wx*(1.f-wy)
                 + v10*(1.f-wx)*wy       + v11*wx*wy;
    } else {
        int j = idx - NPATCH;
        if (j >= NPOS) return;
        const int d = j & 63, bp = j >> 6;
        out[idx] = tp[bp*2] * pos_w[d] + tp[bp*2+1] * pos_w[64 + d] + pos_b[d];
    }
}

// =====================================================================
extern "C" void kernel_launch(void* const* d_in, const int* in_sizes, int n_in,
                              void* d_out, int out_size) {
    const float* x      = (const float*)d_in[0];
    const float* conv_w = (const float*)d_in[1];
    const float* conv_b = (const float*)d_in[2];
    const float* in_w   = (const float*)d_in[3];
    const float* in_b   = (const float*)d_in[4];
    const float* wq     = (const float*)d_in[5];
    const float* bq     = (const float*)d_in[6];
    const float* wk     = (const float*)d_in[7];
    const float* bk     = (const float*)d_in[8];
    const float* wv     = (const float*)d_in[9];
    const float* bv     = (const float*)d_in[10];
    const float* wo     = (const float*)d_in[11];
    const float* bo     = (const float*)d_in[12];
    const float* out_w  = (const float*)d_in[13];
    const float* out_b  = (const float*)d_in[14];
    const float* fc_w   = (const float*)d_in[15];
    const float* fc_b   = (const float*)d_in[16];
    const float* pos_w  = (const float*)d_in[17];
    const float* pos_b  = (const float*)d_in[18];
    float* outp = (float*)d_out;

    __nv_bfloat16 *wH, *wL, *featH, *featL;
    __nv_bfloat16 *inwTh, *inwTl, *qkvwTh, *qkvwTl, *tokH, *tokL, *qkvH, *qkvL;
    float *qkvb, *part, *o, *Mf, *cf, *Mfo, *cfo, *tp;
    cudaGetSymbolAddress((void**)&wH,   g_wH);
    cudaGetSymbolAddress((void**)&wL,   g_wL);
    cudaGetSymbolAddress((void**)&featH, g_featH);
    cudaGetSymbolAddress((void**)&featL, g_featL);
    cudaGetSymbolAddress((void**)&inwTh, g_inwTh);
    cudaGetSymbolAddress((void**)&inwTl, g_inwTl);
    cudaGetSymbolAddress((void**)&qkvwTh, g_qkvwTh);
    cudaGetSymbolAddress((void**)&qkvwTl, g_qkvwTl);
    cudaGetSymbolAddress((void**)&qkvb, g_qkvb);
    cudaGetSymbolAddress((void**)&part, g_part);
    cudaGetSymbolAddress((void**)&tokH, g_tokH);
    cudaGetSymbolAddress((void**)&tokL, g_tokL);
    cudaGetSymbolAddress((void**)&qkvH, g_qkvH);
    cudaGetSymbolAddress((void**)&qkvL, g_qkvL);
    cudaGetSymbolAddress((void**)&o,    g_o);
    cudaGetSymbolAddress((void**)&Mf,   g_Mf);
    cudaGetSymbolAddress((void**)&cf,   g_cf);
    cudaGetSymbolAddress((void**)&Mfo,  g_Mfo);
    cudaGetSymbolAddress((void**)&cfo,  g_cfo);
    cudaGetSymbolAddress((void**)&tp,   g_tp);

    cudaFuncSetAttribute(conv_gemm_kernel, cudaFuncAttributeMaxDynamicSharedMemorySize, GEMM_SMEM);
    cudaFuncSetAttribute(gemm_wmma<1>, cudaFuncAttributeMaxDynamicSharedMemorySize, GEMM_SMEM);
    cudaFuncSetAttribute(gemm_wmma<3>, cudaFuncAttributeMaxDynamicSharedMemorySize, GEMM_SMEM);
    cudaFuncSetAttribute(attn_wmma_kernel, cudaFuncAttributeMaxDynamicSharedMemorySize, ATT_SMEM);

    prep_small_kernel<<<516, 256>>>(conv_w, wH, wL, bq, bk, bv, qkvb,
                                    out_w, out_b, fc_w, fc_b, Mf, cf);               // 0
    transpose_all_kernel<<<dim3(8, 152), dim3(32, 8)>>>(in_w, wq, wk, wv,
                                                        inwTh, inwTl, qkvwTh, qkvwTl); // 1
    fold_kernel<<<E_ + 1, 256>>>(wo, bo, Mf, cf, Mfo, cfo, E_, E_);                  // 2

    // ---- fused im2col + conv GEMM (index 3 = ncu profiled; control) ----
    conv_gemm_kernel<<<dim3(32, 2, 16), 256, GEMM_SMEM>>>(
        wH, wL, x, conv_b, featH, featL);                                            // 3

    // ---- tok = feat @ in_w + in_b (split-K=4) ----
    gemm_wmma<1><<<dim3(2, 32, 4), 256, GEMM_SMEM>>>(
        featH, featL, inwTh, inwTl, HW_, E_, 1024,
        0, (size_t)BP_*E_, 1024,
        nullptr, part, nullptr, nullptr);                                            // 4
    reduce_tok_kernel<<<((BP_*E_)/4 + 255)/256, 256>>>(part, in_b, tokH, tokL);      // 5

    // ---- fused QKV -> bf16 hi/lo ----
    gemm_wmma<3><<<dim3(6, 32, 1), 256, GEMM_SMEM>>>(
        tokH, tokL, qkvwTh, qkvwTl, E_, QKVN, E_,
        0, 0, 0,
        qkvb, nullptr, qkvH, qkvL);                                                  // 6

    // ---- tensor-core attention ----
    attn_wmma_kernel<<<dim3(4, B_*NH_), 256, ATT_SMEM>>>(qkvH, qkvL, o);             // 7

    // ---- tp = tanh(o @ Mfo + cfo) ----
    tp_kernel<<<BP_/4, 128>>>(o, Mfo, cfo, tp);                                      // 8

    // ---- outputs ----
    outputs_kernel<<<(NPATCH + NPOS + 255)/256, 256>>>(x, tp, pos_w, pos_b, outp);   // 9
}

// round 14
// speedup vs baseline: 1.0390x; 1.0390x over previous
#include <cuda_runtime.h>
#include <cuda_bf16.h>
#include <mma.h>
#include <cstdint>
#include <math.h>

using namespace nvcuda;

#define B_    16
#define C_    3
#define H_    64
#define W_    64
#define P_    256
#define PS_   9
#define E_    256
#define NH_   8
#define DH_   32
#define HW_   4096
#define POSD_ 64
#define BP_   (B_*P_)               // 4096
#define NPATCH (B_*P_*C_*PS_*PS_)   // 995328
#define NPOS   (BP_*POSD_)          // 262144
#define QKVN  768
#define KC_   256                   // conv GEMM K (243 padded)

// ---------------- scratch ----------------
__device__ __nv_bfloat16 g_wH [E_*KC_];
__device__ __nv_bfloat16 g_wL [E_*KC_];
__device__ __nv_bfloat16 g_colH[(size_t)B_*HW_*KC_];
__device__ __nv_bfloat16 g_colL[(size_t)B_*HW_*KC_];
__device__ __nv_bfloat16 g_featH[(size_t)BP_*HW_];
__device__ __nv_bfloat16 g_featL[(size_t)BP_*HW_];
__device__ __nv_bfloat16 g_inwTh[(size_t)E_*HW_];
__device__ __nv_bfloat16 g_inwTl[(size_t)E_*HW_];
__device__ __nv_bfloat16 g_qkvwTh[QKVN*E_];
__device__ __nv_bfloat16 g_qkvwTl[QKVN*E_];
__device__ float g_qkvb[QKVN];
__device__ float g_part[4*(size_t)BP_*E_];
__device__ __nv_bfloat16 g_tokH[BP_*E_];
__device__ __nv_bfloat16 g_tokL[BP_*E_];
__device__ __nv_bfloat16 g_qkvH[(size_t)BP_*QKVN];
__device__ __nv_bfloat16 g_qkvL[(size_t)BP_*QKVN];
__device__ float g_o  [BP_*E_];
__device__ float g_Mf [E_*2];
__device__ float g_cf [2];
__device__ float g_Mfo[E_*2];
__device__ float g_cfo[2];
__device__ float g_tp [BP_*2];

// ---------------- cp.async helpers ----------------
__device__ __forceinline__ uint32_t smem_u32(const void* p) {
    uint32_t a;
    asm("{ .reg .u64 t; cvta.to.shared.u64 t, %1; cvt.u32.u64 %0, t; }" : "=r"(a) : "l"(p));
    return a;
}
#define CP_ASYNC16(dst, src) \
    asm volatile("cp.async.cg.shared.global [%0], [%1], 16;" :: "r"(dst), "l"(src))
#define CP_COMMIT() asm volatile("cp.async.commit_group;" ::: "memory")
#define CP_WAIT0()  asm volatile("cp.async.wait_group 0;" ::: "memory")

__device__ __forceinline__ uint2 pack4_bf16(float a, float b, float c, float d) {
    __nv_bfloat162 lo = __floats2bfloat162_rn(a, b);
    __nv_bfloat162 hi = __floats2bfloat162_rn(c, d);
    uint2 r;
    r.x = *(uint32_t*)&lo;
    r.y = *(uint32_t*)&hi;
    return r;
}

// =====================================================================
// prep_small: wprep (0..255) + concat_bias (256..258) + fold1 (259..515)
// =====================================================================
__global__ void prep_small_kernel(const float* __restrict__ conv_w,
                                  __nv_bfloat16* __restrict__ wH,
                                  __nv_bfloat16* __restrict__ wL,
                                  const float* __restrict__ bq,
                                  const float* __restrict__ bk,
                                  const float* __restrict__ bv,
                                  float* __restrict__ qkvb,
                                  const float* __restrict__ out_w,
                                  const float* __restrict__ out_b,
                                  const float* __restrict__ fc_w,
                                  const float* __restrict__ fc_b,
                                  float* __restrict__ Mf,
                                  float* __restrict__ cf) {
    const int bid = blockIdx.x, tid = threadIdx.x;
    if (bid < 256) {
        int idx = bid*256 + tid;
        int oc = idx >> 8, k = idx & 255;
        float v = (k < 243) ? conv_w[oc*243 + k] : 0.f;
        __nv_bfloat16 h = __float2bfloat16(v);
        wH[idx] = h;
        wL[idx] = __float2bfloat16(v - __bfloat162float(h));
        return;
    }
    if (bid < 259) {
        int i = (bid - 256)*256 + tid;
        if (i < 768) qkvb[i] = (i < 256) ? bq[i] : (i < 512 ? bk[i-256] : bv[i-512]);
        return;
    }
    const int e = bid - 259;
    const float* arow = (e < E_) ? (out_w + (size_t)e*HW_) : out_b;
    float s0 = 0.f, s1 = 0.f;
    for (int i = tid; i < HW_; i += 256) {
        float a = arow[i];
        float2 f = *(const float2*)&fc_w[i*2];
        s0 = fmaf(a, f.x, s0);
        s1 = fmaf(a, f.y, s1);
    }
    __shared__ float red0[8], red1[8];
    const int lane = tid & 31, warp = tid >> 5;
#pragma unroll
    for (int o = 16; o; o >>= 1) {
        s0 += __shfl_xor_sync(0xffffffffu, s0, o);
        s1 += __shfl_xor_sync(0xffffffffu, s1, o);
    }
    if (lane == 0) { red0[warp] = s0; red1[warp] = s1; }
    __syncthreads();
    if (tid == 0) {
        float t0 = 0.f, t1 = 0.f;
#pragma unroll
        for (int i = 0; i < 8; i++) { t0 += red0[i]; t1 += red1[i]; }
        if (e < E_) { Mf[e*2] = t0; Mf[e*2+1] = t1; }
        else        { cf[0] = t0 + fc_b[0]; cf[1] = t1 + fc_b[1]; }
    }
}

// =====================================================================
// im2col (vectorized)
// =====================================================================
__global__ void im2col_kernel(const float* __restrict__ x,
                              __nv_bfloat16* __restrict__ colH,
                              __nv_bfloat16* __restrict__ colL) {
    size_t t = (size_t)blockIdx.x*256 + threadIdx.x;
    if (t >= (size_t)B_*HW_*(KC_/4)) return;
    int k4  = (int)(t & 63);
    int pix = (int)((t >> 6) & 4095);
    int b   = (int)(t >> 18);
    const int py = pix >> 6, px = pix & 63;

    float vh[4], vl[4];
#pragma unroll
    for (int u = 0; u < 4; u++) {
        int k = (k4 << 2) + u;
        float v = 0.f;
        if (k < 243) {
            int c  = k / 81;
            int r  = k - c*81;
            int ky = r / 9;
            int kx = r - ky*9;
            int yy = py + ky - 4;
            int xx = px + kx - 4;
            if (yy >= 0 && yy < 64 && xx >= 0 && xx < 64)
                v = x[((size_t)(b*3 + c) << 12) + (yy << 6) + xx];
        }
        float h = __bfloat162float(__float2bfloat16(v));
        vh[u] = v;
        vl[u] = v - h;
    }
    size_t base = ((size_t)b << 20) + ((size_t)pix << 8) + (k4 << 2);
    *(uint2*)(colH + base) = pack4_bf16(vh[0], vh[1], vh[2], vh[3]);
    *(uint2*)(colL + base) = pack4_bf16(vl[0], vl[1], vl[2], vl[3]);
}

// =====================================================================
// Batched transpose + bf16 split
// =====================================================================
__global__ void transpose_all_kernel(const float* __restrict__ in_w,
                                     const float* __restrict__ wq,
                                     const float* __restrict__ wk,
                                     const float* __restrict__ wv,
                                     __nv_bfloat16* __restrict__ inwTh,
                                     __nv_bfloat16* __restrict__ inwTl,
                                     __nv_bfloat16* __restrict__ qkvwTh,
                                     __nv_bfloat16* __restrict__ qkvwTl) {
    __shared__ float tile[32][33];
    const int y = blockIdx.y;
    const float* src; int Kd, k0;
    __nv_bfloat16 *oH, *oL;
    if (y < 128) {
        src = in_w; Kd = HW_; k0 = y << 5; oH = inwTh; oL = inwTl;
    } else {
        int g  = (y - 128) >> 3;
        int yy = (y - 128) & 7;
        src = (g == 0) ? wq : (g == 1) ? wk : wv;
        Kd = E_; k0 = yy << 5;
        oH = qkvwTh + g*256*E_; oL = qkvwTl + g*256*E_;
    }
    const int n0 = blockIdx.x << 5;
    const int tx = threadIdx.x, ty = threadIdx.y;
    for (int i = ty; i < 32; i += 8)
        tile[i][tx] = src[(size_t)(k0 + i)*E_ + n0 + tx];
    __syncthreads();
    for (int i = ty; i < 32; i += 8) {
        float v = tile[tx][i];
        __nv_bfloat16 h = __float2bfloat16(v);
        size_t o = (size_t)(n0 + i)*Kd + k0 + tx;
        oH[o] = h;
        oL[o] = __float2bfloat16(v - __bfloat162float(h));
    }
}

// =====================================================================
// wmma bf16-split GEMM (R12 proven).
// CTA tile 128x128, BK=32, 8 warps (2x4), warp tile 64x32, 2 CTAs/SM.
// MODE 1: C = acc (fp32 partial); MODE 2: relu+bias[row]->bf16 split;
// MODE 3: bias[col]->bf16 split
// =====================================================================
#define LDS_  40
#define TILE_B (128*LDS_*2)
#define STAGE_B (4*TILE_B)
#define GEMM_SMEM (2*STAGE_B)        // 81920 B

template<int MODE>
__global__ __launch_bounds__(256, 2)
void gemm_wmma(const __nv_bfloat16* __restrict__ Ah, const __nv_bfloat16* __restrict__ Al,
               const __nv_bfloat16* __restrict__ Bh, const __nv_bfloat16* __restrict__ Bl,
               int K, int ldc, int kLen, size_t bOffZ, size_t cOffZ, int kOffZ,
               const float* __restrict__ bias, float* __restrict__ C,
               __nv_bfloat16* __restrict__ CH, __nv_bfloat16* __restrict__ CL) {
    extern __shared__ char smem[];
    const int tid = threadIdx.x;
    const int wid = tid >> 5;
    const int warpM = wid & 1;
    const int warpN = wid >> 1;
    const int mBase = blockIdx.y << 7;
    const int nBase = blockIdx.x << 7;
    const int z = blockIdx.z;

    Bh += (size_t)z * bOffZ;  Bl += (size_t)z * bOffZ;
    if (MODE == 2 || MODE == 3) { CH += (size_t)z * cOffZ; CL += (size_t)z * cOffZ; }
    else                          C  += (size_t)z * cOffZ;
    const int k0 = z * kOffZ;

    const __nv_bfloat16* srcs[4] = {
        Ah + (size_t)mBase*K, Al + (size_t)mBase*K,
        Bh + (size_t)nBase*K, Bl + (size_t)nBase*K };

    const uint32_t smemBase = smem_u32(smem);

    auto load_stage = [&](int s, int kg) {
        const uint32_t sb = smemBase + s*STAGE_B;
#pragma unroll
        for (int t = 0; t < 4; t++) {
            const __nv_bfloat16* src = srcs[t];
            const uint32_t dst = sb + t*TILE_B;
#pragma unroll
            for (int i = 0; i < 2; i++) {
                int idx = tid + (i << 8);
                int row = idx >> 2, seg = idx & 3;
                CP_ASYNC16(dst + (uint32_t)(row*(LDS_*2) + seg*16),
                           (const char*)(src + (size_t)row*K + kg + seg*8));
            }
        }
    };

    wmma::fragment<wmma::accumulator, 16,16,16, float> acc[4][2];
#pragma unroll
    for (int i = 0; i < 4; i++)
#pragma unroll
        for (int j = 0; j < 2; j++) wmma::fill_fragment(acc[i][j], 0.f);

    const int nChunks = kLen >> 5;
    load_stage(0, k0); CP_COMMIT();

    for (int c = 0; c < nChunks; c++) {
        CP_WAIT0();
        __syncthreads();
        if (c + 1 < nChunks) { load_stage((c+1) & 1, k0 + ((c+1) << 5)); CP_COMMIT(); }

        const __nv_bfloat16* As_h = (const __nv_bfloat16*)(smem + (c&1)*STAGE_B);
        const __nv_bfloat16* As_l = As_h + 128*LDS_;
        const __nv_bfloat16* Bs_h = As_l + 128*LDS_;
        const __nv_bfloat16* Bs_l = Bs_h + 128*LDS_;

#pragma unroll
        for (int ks = 0; ks < 2; ks++) {
            wmma::fragment<wmma::matrix_a, 16,16,16, __nv_bfloat16, wmma::row_major> a_h[4], a_l[4];
            wmma::fragment<wmma::matrix_b, 16,16,16, __nv_bfloat16, wmma::col_major> b_h[2], b_l[2];
#pragma unroll
            for (int i = 0; i < 4; i++) {
                const int r = (warpM*64 + i*16)*LDS_ + ks*16;
                wmma::load_matrix_sync(a_h[i], As_h + r, LDS_);
                wmma::load_matrix_sync(a_l[i], As_l + r, LDS_);
            }
#pragma unroll
            for (int j = 0; j < 2; j++) {
                const int r = (warpN*32 + j*16)*LDS_ + ks*16;
                wmma::load_matrix_sync(b_h[j], Bs_h + r, LDS_);
                wmma::load_matrix_sync(b_l[j], Bs_l + r, LDS_);
            }
#pragma unroll
            for (int i = 0; i < 4; i++)
#pragma unroll
                for (int j = 0; j < 2; j++) {
                    wmma::mma_sync(acc[i][j], a_h[i], b_h[j], acc[i][j]);
                    wmma::mma_sync(acc[i][j], a_h[i], b_l[j], acc[i][j]);
                    wmma::mma_sync(acc[i][j], a_l[i], b_h[j], acc[i][j]);
                }
        }
    }

    if (MODE == 1) {
#pragma unroll
        for (int i = 0; i < 4; i++)
#pragma unroll
            for (int j = 0; j < 2; j++)
                wmma::store_matrix_sync(
                    C + (size_t)(mBase + warpM*64 + i*16)*ldc + nBase + warpN*32 + j*16,
                    acc[i][j], ldc, wmma::mem_row_major);
        return;
    }

    __syncthreads();
    float* sC = (float*)smem;
#pragma unroll
    for (int i = 0; i < 4; i++)
#pragma unroll
        for (int j = 0; j < 2; j++)
            wmma::store_matrix_sync(sC + (size_t)(warpM*64 + i*16)*128 + warpN*32 + j*16,
                                    acc[i][j], 128, wmma::mem_row_major);
    __syncthreads();

#pragma unroll
    for (int t = 0; t < 16; t++) {
        int lin = tid + (t << 8);
        int row = lin >> 5;
        int col = (lin & 31) << 2;
        float4 v = *(const float4*)(sC + row*128 + col);
        const int gm = mBase + row, gn = nBase + col;
        if (MODE == 3) {
            const float4 bv = *(const float4*)(bias + gn);
            float r0 = v.x + bv.x, r1 = v.y + bv.y, r2 = v.z + bv.z, r3 = v.w + bv.w;
            float h0 = __bfloat162float(__float2bfloat16(r0));
            float h1 = __bfloat162float(__float2bfloat16(r1));
            float h2 = __bfloat162float(__float2bfloat16(r2));
            float h3 = __bfloat162float(__float2bfloat16(r3));
            *(uint2*)(CH + (size_t)gm*ldc + gn) = pack4_bf16(r0, r1, r2, r3);
            *(uint2*)(CL + (size_t)gm*ldc + gn) =
                pack4_bf16(r0 - h0, r1 - h1, r2 - h2, r3 - h3);
        } else {
            const float bb = bias[gm];
            float r0 = fmaxf(v.x + bb, 0.f), r1 = fmaxf(v.y + bb, 0.f);
            float r2 = fmaxf(v.z + bb, 0.f), r3 = fmaxf(v.w + bb, 0.f);
            float h0 = __bfloat162float(__float2bfloat16(r0));
            float h1 = __bfloat162float(__float2bfloat16(r1));
            float h2 = __bfloat162float(__float2bfloat16(r2));
            float h3 = __bfloat162float(__float2bfloat16(r3));
            *(uint2*)(CH + (size_t)gm*ldc + gn) = pack4_bf16(r0, r1, r2, r3);
            *(uint2*)(CL + (size_t)gm*ldc + gn) =
                pack4_bf16(r0 - h0, r1 - h1, r2 - h2, r3 - h3);
        }
    }
}

// reduce split-K partials + bias -> tok bf16 hi/lo (vectorized x4)
__global__ void reduce_tok_kernel(const float* __restrict__ part,
                                  const float* __restrict__ bias,
                                  __nv_bfloat16* __restrict__ tokH,
                                  __nv_bfloat16* __restrict__ tokL) {
    int t = blockIdx.x*256 + threadIdx.x;
    if (t >= (BP_*E_)/4) return;
    const int idx = t << 2;
    const size_t S = (size_t)BP_*E_;
    float4 p0 = *(const float4*)(part + idx);
    float4 p1 = *(const float4*)(part + idx + S);
    float4 p2 = *(const float4*)(part + idx + 2*S);
    float4 p3 = *(const float4*)(part + idx + 3*S);
    float4 bv = *(const float4*)(bias + (idx & 255));
    float v0 = p0.x + p1.x + p2.x + p3.x + bv.x;
    float v1 = p0.y + p1.y + p2.y + p3.y + bv.y;
    float v2 = p0.z + p1.z + p2.z + p3.z + bv.z;
    float v3 = p0.w + p1.w + p2.w + p3.w + bv.w;
    float h0 = __bfloat162float(__float2bfloat16(v0));
    float h1 = __bfloat162float(__float2bfloat16(v1));
    float h2 = __bfloat162float(__float2bfloat16(v2));
    float h3 = __bfloat162float(__float2bfloat16(v3));
    *(uint2*)(tokH + idx) = pack4_bf16(v0, v1, v2, v3);
    *(uint2*)(tokL + idx) = pack4_bf16(v0 - h0, v1 - h1, v2 - h2, v3 - h3);
}

// =====================================================================
// Tensor-core attention (R12 proven)
// =====================================================================
#define ASLD 264
#define ATT_SMEM (64*ASLD*4 + 2*(64*ASLD*2) + 2*(64*40*2) + 4*(256*40*2))  // 227328 B

__global__ __launch_bounds__(256)
void attn_wmma_kernel(const __nv_bfloat16* __restrict__ qkvH,
                      const __nv_bfloat16* __restrict__ qkvL,
                      float* __restrict__ o) {
    extern __shared__ char sm_[];
    float*        sS  = (float*)sm_;
    __nv_bfloat16* sPh = (__nv_bfloat16*)(sS + 64*ASLD);
    __nv_bfloat16* sPl = sPh + 64*ASLD;
    __nv_bfloat16* sQh = sPl + 64*ASLD;
    __nv_bfloat16* sQl = sQh + 64*40;
    __nv_bfloat16* sKh = sQl + 64*40;
    __nv_bfloat16* sKl = sKh + 256*40;
    __nv_bfloat16* sVh = sKl + 256*40;
    __nv_bfloat16* sVl = sVh + 256*40;

    const int bh = blockIdx.y, b = bh >> 3, h = bh & 7;
    const int q0 = blockIdx.x << 6;
    const int tid = threadIdx.x;
    const int wid = tid >> 5;
    const float scale = 0.17677669529663687f;

    const size_t rowQ = (size_t)(b*P_ + q0)*QKVN + h*32;
    const size_t rowK = (size_t)(b*P_)*QKVN + 256 + h*32;
    const size_t rowV = (size_t)(b*P_)*QKVN + 512 + h*32;
    for (int i = tid; i < 512; i += 256) {
        int a = i >> 8, r = (i >> 2) & 63, s = i & 3;
        const __nv_bfloat16* src = (a ? qkvL : qkvH) + rowQ + (size_t)r*QKVN + s*8;
        *(uint4*)((a ? sQl : sQh) + r*40 + s*8) = *(const uint4*)src;
    }
    for (int i = tid; i < 2048; i += 256) {
        int a = i >> 10, r = (i >> 2) & 255, s = i & 3;
        const __nv_bfloat16* srck = (a ? qkvL : qkvH) + rowK + (size_t)r*QKVN + s*8;
        *(uint4*)((a ? sKl : sKh) + r*40 + s*8) = *(const uint4*)srck;
        const __nv_bfloat16* srcv = (a ? qkvL : qkvH) + rowV + (size_t)r*QKVN + s*8;
        *(uint4*)((a ? sVl : sVh) + r*40 + s*8) = *(const uint4*)srcv;
    }
    __syncthreads();

    {
        const int wm = wid & 1, wn = wid >> 1;
        wmma::fragment<wmma::accumulator, 16,16,16, float> acc[2][4];
#pragma unroll
        for (int i = 0; i < 2; i++)
#pragma unroll
            for (int j = 0; j < 4; j++) wmma::fill_fragment(acc[i][j], 0.f);
#pragma unroll
        for (int ks = 0; ks < 2; ks++) {
            wmma::fragment<wmma::matrix_a, 16,16,16, __nv_bfloat16, wmma::row_major> a_h[2], a_l[2];
            wmma::fragment<wmma::matrix_b, 16,16,16, __nv_bfloat16, wmma::col_major> b_h[4], b_l[4];
#pragma unroll
            for (int i = 0; i < 2; i++) {
                const int r = (wm*32 + i*16)*40 + ks*16;
                wmma::load_matrix_sync(a_h[i], sQh + r, 40);
                wmma::load_matrix_sync(a_l[i], sQl + r, 40);
            }
#pragma unroll
            for (int j = 0; j < 4; j++) {
                const int r = (wn*64 + j*16)*40 + ks*16;
                wmma::load_matrix_sync(b_h[j], sKh + r, 40);
                wmma::load_matrix_sync(b_l[j], sKl + r, 40);
            }
#pragma unroll
            for (int i = 0; i < 2; i++)
#pragma unroll
                for (int j = 0; j < 4; j++) {
                    wmma::mma_sync(acc[i][j], a_h[i], b_h[j], acc[i][j]);
                    wmma::mma_sync(acc[i][j], a_h[i], b_l[j], acc[i][j]);
                    wmma::mma_sync(acc[i][j], a_l[i], b_h[j], acc[i][j]);
                }
        }
#pragma unroll
        for (int i = 0; i < 2; i++)
#pragma unroll
            for (int j = 0; j < 4; j++)
                wmma::store_matrix_sync(sS + (wm*32 + i*16)*ASLD + wn*64 + j*16,
                                        acc[i][j], ASLD, wmma::mem_row_major);
    }
    __syncthreads();

    {
        const int warp = wid, lane = tid & 31;
        for (int r = warp; r < 64; r += 8) {
            float4* row = (float4*)(sS + r*ASLD);
            float4 v0 = row[lane], v1 = row[lane + 32];
            v0.x *= scale; v0.y *= scale; v0.z *= scale; v0.w *= scale;
            v1.x *= scale; v1.y *= scale; v1.z *= scale; v1.w *= scale;
            float m = fmaxf(fmaxf(fmaxf(v0.x,v0.y), fmaxf(v0.z,v0.w)),
                            fmaxf(fmaxf(v1.x,v1.y), fmaxf(v1.z,v1.w)));
#pragma unroll
            for (int off = 16; off; off >>= 1) m = fmaxf(m, __shfl_xor_sync(0xffffffffu, m, off));
            v0.x = __expf(v0.x-m); v0.y = __expf(v0.y-m); v0.z = __expf(v0.z-m); v0.w = __expf(v0.w-m);
            v1.x = __expf(v1.x-m); v1.y = __expf(v1.y-m); v1.z = __expf(v1.z-m); v1.w = __expf(v1.w-m);
            float s = v0.x+v0.y+v0.z+v0.w + v1.x+v1.y+v1.z+v1.w;
#pragma unroll
            for (int off = 16; off; off >>= 1) s += __shfl_xor_sync(0xffffffffu, s, off);
            const float inv = 1.f / s;
            v0.x*=inv; v0.y*=inv; v0.z*=inv; v0.w*=inv;
            v1.x*=inv; v1.y*=inv; v1.z*=inv; v1.w*=inv;
            row[lane] = v0; row[lane+32] = v1;
        }
    }
    __syncthreads();

    for (int i = tid; i < 4096; i += 256) {
        int r = i >> 6, g = (i & 63) << 2;
        float4 v = *(const float4*)(sS + r*ASLD + g);
        float h0 = __bfloat162float(__float2bfloat16(v.x));
        float h1 = __bfloat162float(__float2bfloat16(v.y));
        float h2 = __bfloat162float(__float2bfloat16(v.z));
        float h3 = __bfloat162float(__float2bfloat16(v.w));
        *(uint2*)(sPh + r*ASLD + g) = pack4_bf16(v.x, v.y, v.z, v.w);
        *(uint2*)(sPl + r*ASLD + g) = pack4_bf16(v.x - h0, v.y - h1, v.z - h2, v.w - h3);
    }
    __syncthreads();

    {
        const int wm = wid & 3, wn = wid >> 2;
        wmma::fragment<wmma::accumulator, 16,16,16, float> acc;
        wmma::fill_fragment(acc, 0.f);
#pragma unroll
        for (int k = 0; k < 16; k++) {
            wmma::fragment<wmma::matrix_a, 16,16,16, __nv_bfloat16, wmma::row_major> a_h, a_l;
            wmma::fragment<wmma::matrix_b, 16,16,16, __nv_bfloat16, wmma::row_major> b_h, b_l;
            wmma::load_matrix_sync(a_h, sPh + (wm*16)*ASLD + k*16, ASLD);
            wmma::load_matrix_sync(a_l, sPl + (wm*16)*ASLD + k*16, ASLD);
            wmma::load_matrix_sync(b_h, sVh + (k*16)*40 + wn*16, 40);
            wmma::load_matrix_sync(b_l, sVl + (k*16)*40 + wn*16, 40);
            wmma::mma_sync(acc, a_h, b_h, acc);
            wmma::mma_sync(acc, a_h, b_l, acc);
            wmma::mma_sync(acc, a_l, b_h, acc);
        }
        wmma::store_matrix_sync(o + (size_t)(b*P_ + q0 + wm*16)*E_ + h*32 + wn*16,
                                acc, E_, wmma::mem_row_major);
    }
}

// =====================================================================
// fold2 + tail
// =====================================================================
__global__ void fold_kernel(const float* __restrict__ Wm,
                            const float* __restrict__ brow,
                            const float* __restrict__ M2,
                            const float* __restrict__ addc,
                            float* __restrict__ outM,
                            float* __restrict__ outc, int L, int R) {
    const int e = blockIdx.x, tid = threadIdx.x;
    const float* arow = (e < R) ? (Wm + (size_t)e*L) : brow;
    float s0 = 0.f, s1 = 0.f;
    for (int i = tid; i < L; i += 256) {
        float a = arow[i];
        float2 f = *(const float2*)&M2[i*2];
        s0 = fmaf(a, f.x, s0);
        s1 = fmaf(a, f.y, s1);
    }
    __shared__ float red0[8], red1[8];
    const int lane = tid & 31, warp = tid >> 5;
#pragma unroll
    for (int o = 16; o; o >>= 1) {
        s0 += __shfl_xor_sync(0xffffffffu, s0, o);
        s1 += __shfl_xor_sync(0xffffffffu, s1, o);
    }
    if (lane == 0) { red0[warp] = s0; red1[warp] = s1; }
    __syncthreads();
    if (tid == 0) {
        float t0 = 0.f, t1 = 0.f;
#pragma unroll
        for (int i = 0; i < 8; i++) { t0 += red0[i]; t1 += red1[i]; }
        if (e < R) { outM[e*2] = t0; outM[e*2+1] = t1; }
        else {
            float c0 = addc ? addc[0] : 0.f, c1 = addc ? addc[1] : 0.f;
            outc[0] = t0 + c0; outc[1] = t1 + c1;
        }
    }
}

// tp = tanh(o @ Mfo + cfo); warp per row, float4 loads
__global__ void tp_kernel(const float* __restrict__ o,
                          const float* __restrict__ Mfo,
                          const float* __restrict__ cfo,
                          float* __restrict__ tp) {
    const int row  = (blockIdx.x << 3) + (threadIdx.x >> 5);
    const int lane = threadIdx.x & 31;
    const float4 a4 = *(const float4*)(o + (size_t)row*E_ + (lane << 2));
    const float4 b4 = *(const float4*)(o + (size_t)row*E_ + 128 + (lane << 2));
    float s0 = 0.f, s1 = 0.f;
#pragma unroll
    for (int u = 0; u < 4; u++) {
        int e0 = (lane << 2) + u;
        float a = (u==0)?a4.x:(u==1)?a4.y:(u==2)?a4.z:a4.w;
        float b = (u==0)?b4.x:(u==1)?b4.y:(u==2)?b4.z:b4.w;
        float2 m0 = *(const float2*)&Mfo[e0*2];
        float2 m1 = *(const float2*)&Mfo[(e0+128)*2];
        s0 = fmaf(a, m0.x, fmaf(b, m1.x, s0));
        s1 = fmaf(a, m0.y, fmaf(b, m1.y, s1));
    }
#pragma unroll
    for (int off = 16; off; off >>= 1) {
        s0 += __shfl_xor_sync(0xffffffffu, s0, off);
        s1 += __shfl_xor_sync(0xffffffffu, s1, off);
    }
    if (lane == 0) {
        tp[row*2+0] = tanhf(s0 + cfo[0]);
        tp[row*2+1] = tanhf(s1 + cfo[1]);
    }
}

__global__ void outputs_kernel(const float* __restrict__ x,
                               const float* __restrict__ tp,
                               const float* __restrict__ pos_w,
                               const float* __restrict__ pos_b,
                               float* __restrict__ out) {
    int idx = blockIdx.x * blockDim.x + threadIdx.x;
    if (idx < NPATCH) {
        const int pix = idx % 81;
        const int c   = (idx / 81) % 3;
        const int bp  = idx / 243;
        const int iy  = pix / 9, ix = pix % 9;
        const int b   = bp >> 8;

        const float tx = tp[bp*2], ty = tp[bp*2+1];
        const float bx = (2.f*ix + 1.f) / 9.f - 1.f;
        const float by = (2.f*iy + 1.f) / 9.f - 1.f;
        const float gx = 0.140625f * bx + tx;
        const float gy = 0.140625f * by + ty;
        const float ixf = ((gx + 1.f) * 64.f - 1.f) * 0.5f;
        const float iyf = ((gy + 1.f) * 64.f - 1.f) * 0.5f;
        const float x0 = floorf(ixf), y0 = floorf(iyf);
        const float wx = ixf - x0,   wy = iyf - y0;
        const int x0i = min(max((int)x0, 0), 63);
        const int x1i = min(max((int)x0 + 1, 0), 63);
        const int y0i = min(max((int)y0, 0), 63);
        const int y1i = min(max((int)y0 + 1, 0), 63);
        const float* img = x + (size_t)(b*3 + c) * 4096;
        const float v00 = img[y0i*64 + x0i], v01 = img[y0i*64 + x1i];
        const float v10 = img[y1i*64 + x0i], v11 = img[y1i*64 + x1i];
        out[idx] = v00*(1.f-wx)*(1.f-wy) + v01*wx*(1.f-wy)
                 + v10*(1.f-wx)*wy       + v11*wx*wy;
    } else {
        int j = idx - NPATCH;
        if (j >= NPOS) return;
        const int d = j & 63, bp = j >> 6;
        out[idx] = tp[bp*2] * pos_w[d] + tp[bp*2+1] * pos_w[64 + d] + pos_b[d];
    }
}

// =====================================================================
extern "C" void kernel_launch(void* const* d_in, const int* in_sizes, int n_in,
                              void* d_out, int out_size) {
    const float* x      = (const float*)d_in[0];
    const float* conv_w = (const float*)d_in[1];
    const float* conv_b = (const float*)d_in[2];
    const float* in_w   = (const float*)d_in[3];
    const float* in_b   = (const float*)d_in[4];
    const float* wq     = (const float*)d_in[5];
    const float* bq     = (const float*)d_in[6];
    const float* wk     = (const float*)d_in[7];
    const float* bk     = (const float*)d_in[8];
    const float* wv     = (const float*)d_in[9];
    const float* bv     = (const float*)d_in[10];
    const float* wo     = (const float*)d_in[11];
    const float* bo     = (const float*)d_in[12];
    const float* out_w  = (const float*)d_in[13];
    const float* out_b  = (const float*)d_in[14];
    const float* fc_w   = (const float*)d_in[15];
    const float* fc_b   = (const float*)d_in[16];
    const float* pos_w  = (const float*)d_in[17];
    const float* pos_b  = (const float*)d_in[18];
    float* outp = (float*)d_out;

    __nv_bfloat16 *wH, *wL, *colH, *colL, *featH, *featL;
    __nv_bfloat16 *inwTh, *inwTl, *qkvwTh, *qkvwTl, *tokH, *tokL, *qkvH, *qkvL;
    float *qkvb, *part, *o, *Mf, *cf, *Mfo, *cfo, *tp;
    cudaGetSymbolAddress((void**)&wH,   g_wH);
    cudaGetSymbolAddress((void**)&wL,   g_wL);
    cudaGetSymbolAddress((void**)&colH, g_colH);
    cudaGetSymbolAddress((void**)&colL, g_colL);
    cudaGetSymbolAddress((void**)&featH, g_featH);
    cudaGetSymbolAddress((void**)&featL, g_featL);
    cudaGetSymbolAddress((void**)&inwTh, g_inwTh);
    cudaGetSymbolAddress((void**)&inwTl, g_inwTl);
    cudaGetSymbolAddress((void**)&qkvwTh, g_qkvwTh);
    cudaGetSymbolAddress((void**)&qkvwTl, g_qkvwTl);
    cudaGetSymbolAddress((void**)&qkvb, g_qkvb);
    cudaGetSymbolAddress((void**)&part, g_part);
    cudaGetSymbolAddress((void**)&tokH, g_tokH);
    cudaGetSymbolAddress((void**)&tokL, g_tokL);
    cudaGetSymbolAddress((void**)&qkvH, g_qkvH);
    cudaGetSymbolAddress((void**)&qkvL, g_qkvL);
    cudaGetSymbolAddress((void**)&o,    g_o);
    cudaGetSymbolAddress((void**)&Mf,   g_Mf);
    cudaGetSymbolAddress((void**)&cf,   g_cf);
    cudaGetSymbolAddress((void**)&Mfo,  g_Mfo);
    cudaGetSymbolAddress((void**)&cfo,  g_cfo);
    cudaGetSymbolAddress((void**)&tp,   g_tp);

    cudaFuncSetAttribute(gemm_wmma<1>, cudaFuncAttributeMaxDynamicSharedMemorySize, GEMM_SMEM);
    cudaFuncSetAttribute(gemm_wmma<2>, cudaFuncAttributeMaxDynamicSharedMemorySize, GEMM_SMEM);
    cudaFuncSetAttribute(gemm_wmma<3>, cudaFuncAttributeMaxDynamicSharedMemorySize, GEMM_SMEM);
    cudaFuncSetAttribute(attn_wmma_kernel, cudaFuncAttributeMaxDynamicSharedMemorySize, ATT_SMEM);

    prep_small_kernel<<<516, 256>>>(conv_w, wH, wL, bq, bk, bv, qkvb,
                                    out_w, out_b, fc_w, fc_b, Mf, cf);               // 0
    im2col_kernel<<<(int)(((size_t)B_*HW_*(KC_/4) + 255)/256), 256>>>(x, colH, colL);// 1
    transpose_all_kernel<<<dim3(8, 152), dim3(32, 8)>>>(in_w, wq, wk, wv,
                                                        inwTh, inwTl, qkvwTh, qkvwTl); // 2

    // ---- conv as GEMM (index 3 = ncu profiled; control) ----
    gemm_wmma<2><<<dim3(32, 2, 16), 256, GEMM_SMEM>>>(
        wH, wL, colH, colL, KC_, HW_, KC_,
        (size_t)HW_*KC_, (size_t)E_*HW_, 0,
        conv_b, nullptr, featH, featL);                                              // 3

    fold_kernel<<<E_ + 1, 256>>>(wo, bo, Mf, cf, Mfo, cfo, E_, E_);                  // 4

    // ---- tok = feat @ in_w + in_b (split-K=4) ----
    gemm_wmma<1><<<dim3(2, 32, 4), 256, GEMM_SMEM>>>(
        featH, featL, inwTh, inwTl, HW_, E_, 1024,
        0, (size_t)BP_*E_, 1024,
        nullptr, part, nullptr, nullptr);                                            // 5
    reduce_tok_kernel<<<((BP_*E_)/4 + 255)/256, 256>>>(part, in_b, tokH, tokL);      // 6

    // ---- fused QKV -> bf16 hi/lo ----
    gemm_wmma<3><<<dim3(6, 32, 1), 256, GEMM_SMEM>>>(
        tokH, tokL, qkvwTh, qkvwTl, E_, QKVN, E_,
        0, 0, 0,
        qkvb, nullptr, qkvH, qkvL);                                                  // 7

    // ---- tensor-core attention ----
    attn_wmma_kernel<<<dim3(4, B_*NH_), 256, ATT_SMEM>>>(qkvH, qkvL, o);             // 8

    // ---- tp = tanh(o @ Mfo + cfo) ----
    tp_kernel<<<BP_/8, 256>>>(o, Mfo, cfo, tp);                                      // 9

    // ---- outputs ----
    outputs_kernel<<<(NPATCH + NPOS + 255)/256, 256>>>(x, tp, pos_w, pos_b, outp);   // 10
}

// round 15
// speedup vs baseline: 1.0426x; 1.0034x over previous
#include <cuda_runtime.h>
#include <cuda_bf16.h>
#include <mma.h>
#include <cstdint>
#include <math.h>

using namespace nvcuda;

#define B_    16
#define C_    3
#define H_    64
#define W_    64
#define P_    256
#define PS_   9
#define E_    256
#define NH_   8
#define DH_   32
#define HW_   4096
#define POSD_ 64
#define BP_   (B_*P_)               // 4096
#define NPATCH (B_*P_*C_*PS_*PS_)   // 995328
#define NPOS   (BP_*POSD_)          // 262144
#define QKVN  768
#define KC_   256                   // conv GEMM K (243 padded)

// ---------------- scratch ----------------
__device__ __nv_bfloat16 g_wH [E_*KC_];
__device__ __nv_bfloat16 g_wL [E_*KC_];
__device__ __nv_bfloat16 g_colH[(size_t)B_*HW_*KC_];
__device__ __nv_bfloat16 g_colL[(size_t)B_*HW_*KC_];
__device__ __nv_bfloat16 g_featH[(size_t)BP_*HW_];
__device__ __nv_bfloat16 g_featL[(size_t)BP_*HW_];
__device__ __nv_bfloat16 g_inwTh[(size_t)E_*HW_];
__device__ __nv_bfloat16 g_inwTl[(size_t)E_*HW_];
__device__ __nv_bfloat16 g_qkvwTh[QKVN*E_];
__device__ __nv_bfloat16 g_qkvwTl[QKVN*E_];
__device__ float g_qkvb[QKVN];
__device__ float g_part[4*(size_t)BP_*E_];
__device__ __nv_bfloat16 g_tokH[BP_*E_];
__device__ __nv_bfloat16 g_tokL[BP_*E_];
__device__ __nv_bfloat16 g_qkvH[(size_t)BP_*QKVN];
__device__ __nv_bfloat16 g_qkvL[(size_t)BP_*QKVN];
__device__ float g_o  [BP_*E_];
__device__ float g_Mf [E_*2];
__device__ float g_cf [2];
__device__ float g_Mfo[E_*2];
__device__ float g_cfo[2];
__device__ float g_tp [BP_*2];

// ---------------- cp.async helpers ----------------
__device__ __forceinline__ uint32_t smem_u32(const void* p) {
    uint32_t a;
    asm("{ .reg .u64 t; cvta.to.shared.u64 t, %1; cvt.u32.u64 %0, t; }" : "=r"(a) : "l"(p));
    return a;
}
#define CP_ASYNC16(dst, src) \
    asm volatile("cp.async.cg.shared.global [%0], [%1], 16;" :: "r"(dst), "l"(src))
#define CP_COMMIT() asm volatile("cp.async.commit_group;" ::: "memory")
#define CP_WAIT0()  asm volatile("cp.async.wait_group 0;" ::: "memory")

__device__ __forceinline__ uint2 pack4_bf16(float a, float b, float c, float d) {
    __nv_bfloat162 lo = __floats2bfloat162_rn(a, b);
    __nv_bfloat162 hi = __floats2bfloat162_rn(c, d);
    uint2 r;
    r.x = *(uint32_t*)&lo;
    r.y = *(uint32_t*)&hi;
    return r;
}

// =====================================================================
// prep_small: wprep (0..255) + concat_bias (256..258) + fold1 (259..515)
// =====================================================================
__global__ void prep_small_kernel(const float* __restrict__ conv_w,
                                  __nv_bfloat16* __restrict__ wH,
                                  __nv_bfloat16* __restrict__ wL,
                                  const float* __restrict__ bq,
                                  const float* __restrict__ bk,
                                  const float* __restrict__ bv,
                                  float* __restrict__ qkvb,
                                  const float* __restrict__ out_w,
                                  const float* __restrict__ out_b,
                                  const float* __restrict__ fc_w,
                                  const float* __restrict__ fc_b,
                                  float* __restrict__ Mf,
                                  float* __restrict__ cf) {
    const int bid = blockIdx.x, tid = threadIdx.x;
    if (bid < 256) {
        int idx = bid*256 + tid;
        int oc = idx >> 8, k = idx & 255;
        float v = (k < 243) ? conv_w[oc*243 + k] : 0.f;
        __nv_bfloat16 h = __float2bfloat16(v);
        wH[idx] = h;
        wL[idx] = __float2bfloat16(v - __bfloat162float(h));
        return;
    }
    if (bid < 259) {
        int i = (bid - 256)*256 + tid;
        if (i < 768) qkvb[i] = (i < 256) ? bq[i] : (i < 512 ? bk[i-256] : bv[i-512]);
        return;
    }
    const int e = bid - 259;
    const float* arow = (e < E_) ? (out_w + (size_t)e*HW_) : out_b;
    float s0 = 0.f, s1 = 0.f;
    for (int i = tid; i < HW_; i += 256) {
        float a = arow[i];
        float2 f = *(const float2*)&fc_w[i*2];
        s0 = fmaf(a, f.x, s0);
        s1 = fmaf(a, f.y, s1);
    }
    __shared__ float red0[8], red1[8];
    const int lane = tid & 31, warp = tid >> 5;
#pragma unroll
    for (int o = 16; o; o >>= 1) {
        s0 += __shfl_xor_sync(0xffffffffu, s0, o);
        s1 += __shfl_xor_sync(0xffffffffu, s1, o);
    }
    if (lane == 0) { red0[warp] = s0; red1[warp] = s1; }
    __syncthreads();
    if (tid == 0) {
        float t0 = 0.f, t1 = 0.f;
#pragma unroll
        for (int i = 0; i < 8; i++) { t0 += red0[i]; t1 += red1[i]; }
        if (e < E_) { Mf[e*2] = t0; Mf[e*2+1] = t1; }
        else        { cf[0] = t0 + fc_b[0]; cf[1] = t1 + fc_b[1]; }
    }
}

// =====================================================================
// im2col (vectorized)
// =====================================================================
__global__ void im2col_kernel(const float* __restrict__ x,
                              __nv_bfloat16* __restrict__ colH,
                              __nv_bfloat16* __restrict__ colL) {
    size_t t = (size_t)blockIdx.x*256 + threadIdx.x;
    if (t >= (size_t)B_*HW_*(KC_/4)) return;
    int k4  = (int)(t & 63);
    int pix = (int)((t >> 6) & 4095);
    int b   = (int)(t >> 18);
    const int py = pix >> 6, px = pix & 63;

    float vh[4], vl[4];
#pragma unroll
    for (int u = 0; u < 4; u++) {
        int k = (k4 << 2) + u;
        float v = 0.f;
        if (k < 243) {
            int c  = k / 81;
            int r  = k - c*81;
            int ky = r / 9;
            int kx = r - ky*9;
            int yy = py + ky - 4;
            int xx = px + kx - 4;
            if (yy >= 0 && yy < 64 && xx >= 0 && xx < 64)
                v = x[((size_t)(b*3 + c) << 12) + (yy << 6) + xx];
        }
        float h = __bfloat162float(__float2bfloat16(v));
        vh[u] = v;
        vl[u] = v - h;
    }
    size_t base = ((size_t)b << 20) + ((size_t)pix << 8) + (k4 << 2);
    *(uint2*)(colH + base) = pack4_bf16(vh[0], vh[1], vh[2], vh[3]);
    *(uint2*)(colL + base) = pack4_bf16(vl[0], vl[1], vl[2], vl[3]);
}

// =====================================================================
// Batched transpose + bf16 split
// =====================================================================
__global__ void transpose_all_kernel(const float* __restrict__ in_w,
                                     const float* __restrict__ wq,
                                     const float* __restrict__ wk,
                                     const float* __restrict__ wv,
                                     __nv_bfloat16* __restrict__ inwTh,
                                     __nv_bfloat16* __restrict__ inwTl,
                                     __nv_bfloat16* __restrict__ qkvwTh,
                                     __nv_bfloat16* __restrict__ qkvwTl) {
    __shared__ float tile[32][33];
    const int y = blockIdx.y;
    const float* src; int Kd, k0;
    __nv_bfloat16 *oH, *oL;
    if (y < 128) {
        src = in_w; Kd = HW_; k0 = y << 5; oH = inwTh; oL = inwTl;
    } else {
        int g  = (y - 128) >> 3;
        int yy = (y - 128) & 7;
        src = (g == 0) ? wq : (g == 1) ? wk : wv;
        Kd = E_; k0 = yy << 5;
        oH = qkvwTh + g*256*E_; oL = qkvwTl + g*256*E_;
    }
    const int n0 = blockIdx.x << 5;
    const int tx = threadIdx.x, ty = threadIdx.y;
    for (int i = ty; i < 32; i += 8)
        tile[i][tx] = src[(size_t)(k0 + i)*E_ + n0 + tx];
    __syncthreads();
    for (int i = ty; i < 32; i += 8) {
        float v = tile[tx][i];
        __nv_bfloat16 h = __float2bfloat16(v);
        size_t o = (size_t)(n0 + i)*Kd + k0 + tx;
        oH[o] = h;
        oL[o] = __float2bfloat16(v - __bfloat162float(h));
    }
}

// =====================================================================
// wmma bf16-split GEMM (proven best config).
// CTA tile 128x128, BK=32, 8 warps (2x4), warp tile 64x32, 2 CTAs/SM.
// MODE 1: C = acc (fp32 partial); MODE 2: relu+bias[row]->bf16 split;
// MODE 3: bias[col]->bf16 split
// =====================================================================
#define LDS_  40
#define TILE_B (128*LDS_*2)
#define STAGE_B (4*TILE_B)
#define GEMM_SMEM (2*STAGE_B)        // 81920 B

template<int MODE>
__global__ __launch_bounds__(256, 2)
void gemm_wmma(const __nv_bfloat16* __restrict__ Ah, const __nv_bfloat16* __restrict__ Al,
               const __nv_bfloat16* __restrict__ Bh, const __nv_bfloat16* __restrict__ Bl,
               int K, int ldc, int kLen, size_t bOffZ, size_t cOffZ, int kOffZ,
               const float* __restrict__ bias, float* __restrict__ C,
               __nv_bfloat16* __restrict__ CH, __nv_bfloat16* __restrict__ CL) {
    extern __shared__ char smem[];
    const int tid = threadIdx.x;
    const int wid = tid >> 5;
    const int warpM = wid & 1;
    const int warpN = wid >> 1;
    const int mBase = blockIdx.y << 7;
    const int nBase = blockIdx.x << 7;
    const int z = blockIdx.z;

    Bh += (size_t)z * bOffZ;  Bl += (size_t)z * bOffZ;
    if (MODE == 2 || MODE == 3) { CH += (size_t)z * cOffZ; CL += (size_t)z * cOffZ; }
    else                          C  += (size_t)z * cOffZ;
    const int k0 = z * kOffZ;

    const __nv_bfloat16* srcs[4] = {
        Ah + (size_t)mBase*K, Al + (size_t)mBase*K,
        Bh + (size_t)nBase*K, Bl + (size_t)nBase*K };

    const uint32_t smemBase = smem_u32(smem);

    auto load_stage = [&](int s, int kg) {
        const uint32_t sb = smemBase + s*STAGE_B;
#pragma unroll
        for (int t = 0; t < 4; t++) {
            const __nv_bfloat16* src = srcs[t];
            const uint32_t dst = sb + t*TILE_B;
#pragma unroll
            for (int i = 0; i < 2; i++) {
                int idx = tid + (i << 8);
                int row = idx >> 2, seg = idx & 3;
                CP_ASYNC16(dst + (uint32_t)(row*(LDS_*2) + seg*16),
                           (const char*)(src + (size_t)row*K + kg + seg*8));
            }
        }
    };

    wmma::fragment<wmma::accumulator, 16,16,16, float> acc[4][2];
#pragma unroll
    for (int i = 0; i < 4; i++)
#pragma unroll
        for (int j = 0; j < 2; j++) wmma::fill_fragment(acc[i][j], 0.f);

    const int nChunks = kLen >> 5;
    load_stage(0, k0); CP_COMMIT();

    for (int c = 0; c < nChunks; c++) {
        CP_WAIT0();
        __syncthreads();
        if (c + 1 < nChunks) { load_stage((c+1) & 1, k0 + ((c+1) << 5)); CP_COMMIT(); }

        const __nv_bfloat16* As_h = (const __nv_bfloat16*)(smem + (c&1)*STAGE_B);
        const __nv_bfloat16* As_l = As_h + 128*LDS_;
        const __nv_bfloat16* Bs_h = As_l + 128*LDS_;
        const __nv_bfloat16* Bs_l = Bs_h + 128*LDS_;

#pragma unroll
        for (int ks = 0; ks < 2; ks++) {
            wmma::fragment<wmma::matrix_a, 16,16,16, __nv_bfloat16, wmma::row_major> a_h[4], a_l[4];
            wmma::fragment<wmma::matrix_b, 16,16,16, __nv_bfloat16, wmma::col_major> b_h[2], b_l[2];
#pragma unroll
            for (int i = 0; i < 4; i++) {
                const int r = (warpM*64 + i*16)*LDS_ + ks*16;
                wmma::load_matrix_sync(a_h[i], As_h + r, LDS_);
                wmma::load_matrix_sync(a_l[i], As_l + r, LDS_);
            }
#pragma unroll
            for (int j = 0; j < 2; j++) {
                const int r = (warpN*32 + j*16)*LDS_ + ks*16;
                wmma::load_matrix_sync(b_h[j], Bs_h + r, LDS_);
                wmma::load_matrix_sync(b_l[j], Bs_l + r, LDS_);
            }
#pragma unroll
            for (int i = 0; i < 4; i++)
#pragma unroll
                for (int j = 0; j < 2; j++) {
                    wmma::mma_sync(acc[i][j], a_h[i], b_h[j], acc[i][j]);
                    wmma::mma_sync(acc[i][j], a_h[i], b_l[j], acc[i][j]);
                    wmma::mma_sync(acc[i][j], a_l[i], b_h[j], acc[i][j]);
                }
        }
    }

    if (MODE == 1) {
#pragma unroll
        for (int i = 0; i < 4; i++)
#pragma unroll
            for (int j = 0; j < 2; j++)
                wmma::store_matrix_sync(
                    C + (size_t)(mBase + warpM*64 + i*16)*ldc + nBase + warpN*32 + j*16,
                    acc[i][j], ldc, wmma::mem_row_major);
        return;
    }

    __syncthreads();
    float* sC = (float*)smem;
#pragma unroll
    for (int i = 0; i < 4; i++)
#pragma unroll
        for (int j = 0; j < 2; j++)
            wmma::store_matrix_sync(sC + (size_t)(warpM*64 + i*16)*128 + warpN*32 + j*16,
                                    acc[i][j], 128, wmma::mem_row_major);
    __syncthreads();

#pragma unroll
    for (int t = 0; t < 16; t++) {
        int lin = tid + (t << 8);
        int row = lin >> 5;
        int col = (lin & 31) << 2;
        float4 v = *(const float4*)(sC + row*128 + col);
        const int gm = mBase + row, gn = nBase + col;
        if (MODE == 3) {
            const float4 bv = *(const float4*)(bias + gn);
            float r0 = v.x + bv.x, r1 = v.y + bv.y, r2 = v.z + bv.z, r3 = v.w + bv.w;
            float h0 = __bfloat162float(__float2bfloat16(r0));
            float h1 = __bfloat162float(__float2bfloat16(r1));
            float h2 = __bfloat162float(__float2bfloat16(r2));
            float h3 = __bfloat162float(__float2bfloat16(r3));
            *(uint2*)(CH + (size_t)gm*ldc + gn) = pack4_bf16(r0, r1, r2, r3);
            *(uint2*)(CL + (size_t)gm*ldc + gn) =
                pack4_bf16(r0 - h0, r1 - h1, r2 - h2, r3 - h3);
        } else {
            const float bb = bias[gm];
            float r0 = fmaxf(v.x + bb, 0.f), r1 = fmaxf(v.y + bb, 0.f);
            float r2 = fmaxf(v.z + bb, 0.f), r3 = fmaxf(v.w + bb, 0.f);
            float h0 = __bfloat162float(__float2bfloat16(r0));
            float h1 = __bfloat162float(__float2bfloat16(r1));
            float h2 = __bfloat162float(__float2bfloat16(r2));
            float h3 = __bfloat162float(__float2bfloat16(r3));
            *(uint2*)(CH + (size_t)gm*ldc + gn) = pack4_bf16(r0, r1, r2, r3);
            *(uint2*)(CL + (size_t)gm*ldc + gn) =
                pack4_bf16(r0 - h0, r1 - h1, r2 - h2, r3 - h3);
        }
    }
}

// reduce split-K partials + bias -> tok bf16 hi/lo (vectorized x4)
__global__ void reduce_tok_kernel(const float* __restrict__ part,
                                  const float* __restrict__ bias,
                                  __nv_bfloat16* __restrict__ tokH,
                                  __nv_bfloat16* __restrict__ tokL) {
    int t = blockIdx.x*256 + threadIdx.x;
    if (t >= (BP_*E_)/4) return;
    const int idx = t << 2;
    const size_t S = (size_t)BP_*E_;
    float4 p0 = *(const float4*)(part + idx);
    float4 p1 = *(const float4*)(part + idx + S);
    float4 p2 = *(const float4*)(part + idx + 2*S);
    float4 p3 = *(const float4*)(part + idx + 3*S);
    float4 bv = *(const float4*)(bias + (idx & 255));
    float v0 = p0.x + p1.x + p2.x + p3.x + bv.x;
    float v1 = p0.y + p1.y + p2.y + p3.y + bv.y;
    float v2 = p0.z + p1.z + p2.z + p3.z + bv.z;
    float v3 = p0.w + p1.w + p2.w + p3.w + bv.w;
    float h0 = __bfloat162float(__float2bfloat16(v0));
    float h1 = __bfloat162float(__float2bfloat16(v1));
    float h2 = __bfloat162float(__float2bfloat16(v2));
    float h3 = __bfloat162float(__float2bfloat16(v3));
    *(uint2*)(tokH + idx) = pack4_bf16(v0, v1, v2, v3);
    *(uint2*)(tokL + idx) = pack4_bf16(v0 - h0, v1 - h1, v2 - h2, v3 - h3);
}

// =====================================================================
// Tensor-core attention (R12 proven)
// =====================================================================
#define ASLD 264
#define ATT_SMEM (64*ASLD*4 + 2*(64*ASLD*2) + 2*(64*40*2) + 4*(256*40*2))  // 227328 B

__global__ __launch_bounds__(256)
void attn_wmma_kernel(const __nv_bfloat16* __restrict__ qkvH,
                      const __nv_bfloat16* __restrict__ qkvL,
                      float* __restrict__ o) {
    extern __shared__ char sm_[];
    float*        sS  = (float*)sm_;
    __nv_bfloat16* sPh = (__nv_bfloat16*)(sS + 64*ASLD);
    __nv_bfloat16* sPl = sPh + 64*ASLD;
    __nv_bfloat16* sQh = sPl + 64*ASLD;
    __nv_bfloat16* sQl = sQh + 64*40;
    __nv_bfloat16* sKh = sQl + 64*40;
    __nv_bfloat16* sKl = sKh + 256*40;
    __nv_bfloat16* sVh = sKl + 256*40;
    __nv_bfloat16* sVl = sVh + 256*40;

    const int bh = blockIdx.y, b = bh >> 3, h = bh & 7;
    const int q0 = blockIdx.x << 6;
    const int tid = threadIdx.x;
    const int wid = tid >> 5;
    const float scale = 0.17677669529663687f;

    const size_t rowQ = (size_t)(b*P_ + q0)*QKVN + h*32;
    const size_t rowK = (size_t)(b*P_)*QKVN + 256 + h*32;
    const size_t rowV = (size_t)(b*P_)*QKVN + 512 + h*32;
    for (int i = tid; i < 512; i += 256) {
        int a = i >> 8, r = (i >> 2) & 63, s = i & 3;
        const __nv_bfloat16* src = (a ? qkvL : qkvH) + rowQ + (size_t)r*QKVN + s*8;
        *(uint4*)((a ? sQl : sQh) + r*40 + s*8) = *(const uint4*)src;
    }
    for (int i = tid; i < 2048; i += 256) {
        int a = i >> 10, r = (i >> 2) & 255, s = i & 3;
        const __nv_bfloat16* srck = (a ? qkvL : qkvH) + rowK + (size_t)r*QKVN + s*8;
        *(uint4*)((a ? sKl : sKh) + r*40 + s*8) = *(const uint4*)srck;
        const __nv_bfloat16* srcv = (a ? qkvL : qkvH) + rowV + (size_t)r*QKVN + s*8;
        *(uint4*)((a ? sVl : sVh) + r*40 + s*8) = *(const uint4*)srcv;
    }
    __syncthreads();

    {
        const int wm = wid & 1, wn = wid >> 1;
        wmma::fragment<wmma::accumulator, 16,16,16, float> acc[2][4];
#pragma unroll
        for (int i = 0; i < 2; i++)
#pragma unroll
            for (int j = 0; j < 4; j++) wmma::fill_fragment(acc[i][j], 0.f);
#pragma unroll
        for (int ks = 0; ks < 2; ks++) {
            wmma::fragment<wmma::matrix_a, 16,16,16, __nv_bfloat16, wmma::row_major> a_h[2], a_l[2];
            wmma::fragment<wmma::matrix_b, 16,16,16, __nv_bfloat16, wmma::col_major> b_h[4], b_l[4];
#pragma unroll
            for (int i = 0; i < 2; i++) {
                const int r = (wm*32 + i*16)*40 + ks*16;
                wmma::load_matrix_sync(a_h[i], sQh + r, 40);
                wmma::load_matrix_sync(a_l[i], sQl + r, 40);
            }
#pragma unroll
            for (int j = 0; j < 4; j++) {
                const int r = (wn*64 + j*16)*40 + ks*16;
                wmma::load_matrix_sync(b_h[j], sKh + r, 40);
                wmma::load_matrix_sync(b_l[j], sKl + r, 40);
            }
#pragma unroll
            for (int i = 0; i < 2; i++)
#pragma unroll
                for (int j = 0; j < 4; j++) {
                    wmma::mma_sync(acc[i][j], a_h[i], b_h[j], acc[i][j]);
                    wmma::mma_sync(acc[i][j], a_h[i], b_l[j], acc[i][j]);
                    wmma::mma_sync(acc[i][j], a_l[i], b_h[j], acc[i][j]);
                }
        }
#pragma unroll
        for (int i = 0; i < 2; i++)
#pragma unroll
            for (int j = 0; j < 4; j++)
                wmma::store_matrix_sync(sS + (wm*32 + i*16)*ASLD + wn*64 + j*16,
                                        acc[i][j], ASLD, wmma::mem_row_major);
    }
    __syncthreads();

    {
        const int warp = wid, lane = tid & 31;
        for (int r = warp; r < 64; r += 8) {
            float4* row = (float4*)(sS + r*ASLD);
            float4 v0 = row[lane], v1 = row[lane + 32];
            v0.x *= scale; v0.y *= scale; v0.z *= scale; v0.w *= scale;
            v1.x *= scale; v1.y *= scale; v1.z *= scale; v1.w *= scale;
            float m = fmaxf(fmaxf(fmaxf(v0.x,v0.y), fmaxf(v0.z,v0.w)),
                            fmaxf(fmaxf(v1.x,v1.y), fmaxf(v1.z,v1.w)));
#pragma unroll
            for (int off = 16; off; off >>= 1) m = fmaxf(m, __shfl_xor_sync(0xffffffffu, m, off));
            v0.x = __expf(v0.x-m); v0.y = __expf(v0.y-m); v0.z = __expf(v0.z-m); v0.w = __expf(v0.w-m);
            v1.x = __expf(v1.x-m); v1.y = __expf(v1.y-m); v1.z = __expf(v1.z-m); v1.w = __expf(v1.w-m);
            float s = v0.x+v0.y+v0.z+v0.w + v1.x+v1.y+v1.z+v1.w;
#pragma unroll
            for (int off = 16; off; off >>= 1) s += __shfl_xor_sync(0xffffffffu, s, off);
            const float inv = 1.f / s;
            v0.x*=inv; v0.y*=inv; v0.z*=inv; v0.w*=inv;
            v1.x*=inv; v1.y*=inv; v1.z*=inv; v1.w*=inv;
            row[lane] = v0; row[lane+32] = v1;
        }
    }
    __syncthreads();

    for (int i = tid; i < 4096; i += 256) {
        int r = i >> 6, g = (i & 63) << 2;
        float4 v = *(const float4*)(sS + r*ASLD + g);
        float h0 = __bfloat162float(__float2bfloat16(v.x));
        float h1 = __bfloat162float(__float2bfloat16(v.y));
        float h2 = __bfloat162float(__float2bfloat16(v.z));
        float h3 = __bfloat162float(__float2bfloat16(v.w));
        *(uint2*)(sPh + r*ASLD + g) = pack4_bf16(v.x, v.y, v.z, v.w);
        *(uint2*)(sPl + r*ASLD + g) = pack4_bf16(v.x - h0, v.y - h1, v.z - h2, v.w - h3);
    }
    __syncthreads();

    {
        const int wm = wid & 3, wn = wid >> 2;
        wmma::fragment<wmma::accumulator, 16,16,16, float> acc;
        wmma::fill_fragment(acc, 0.f);
#pragma unroll
        for (int k = 0; k < 16; k++) {
            wmma::fragment<wmma::matrix_a, 16,16,16, __nv_bfloat16, wmma::row_major> a_h, a_l;
            wmma::fragment<wmma::matrix_b, 16,16,16, __nv_bfloat16, wmma::row_major> b_h, b_l;
            wmma::load_matrix_sync(a_h, sPh + (wm*16)*ASLD + k*16, ASLD);
            wmma::load_matrix_sync(a_l, sPl + (wm*16)*ASLD + k*16, ASLD);
            wmma::load_matrix_sync(b_h, sVh + (k*16)*40 + wn*16, 40);
            wmma::load_matrix_sync(b_l, sVl + (k*16)*40 + wn*16, 40);
            wmma::mma_sync(acc, a_h, b_h, acc);
            wmma::mma_sync(acc, a_h, b_l, acc);
            wmma::mma_sync(acc, a_l, b_h, acc);
        }
        wmma::store_matrix_sync(o + (size_t)(b*P_ + q0 + wm*16)*E_ + h*32 + wn*16,
                                acc, E_, wmma::mem_row_major);
    }
}

// =====================================================================
// fold2 + tail
// =====================================================================
__global__ void fold_kernel(const float* __restrict__ Wm,
                            const float* __restrict__ brow,
                            const float* __restrict__ M2,
                            const float* __restrict__ addc,
                            float* __restrict__ outM,
                            float* __restrict__ outc, int L, int R) {
    const int e = blockIdx.x, tid = threadIdx.x;
    const float* arow = (e < R) ? (Wm + (size_t)e*L) : brow;
    float s0 = 0.f, s1 = 0.f;
    for (int i = tid; i < L; i += 256) {
        float a = arow[i];
        float2 f = *(const float2*)&M2[i*2];
        s0 = fmaf(a, f.x, s0);
        s1 = fmaf(a, f.y, s1);
    }
    __shared__ float red0[8], red1[8];
    const int lane = tid & 31, warp = tid >> 5;
#pragma unroll
    for (int o = 16; o; o >>= 1) {
        s0 += __shfl_xor_sync(0xffffffffu, s0, o);
        s1 += __shfl_xor_sync(0xffffffffu, s1, o);
    }
    if (lane == 0) { red0[warp] = s0; red1[warp] = s1; }
    __syncthreads();
    if (tid == 0) {
        float t0 = 0.f, t1 = 0.f;
#pragma unroll
        for (int i = 0; i < 8; i++) { t0 += red0[i]; t1 += red1[i]; }
        if (e < R) { outM[e*2] = t0; outM[e*2+1] = t1; }
        else {
            float c0 = addc ? addc[0] : 0.f, c1 = addc ? addc[1] : 0.f;
            outc[0] = t0 + c0; outc[1] = t1 + c1;
        }
    }
}

// tp = tanh(o @ Mfo + cfo); warp per row, float4 loads
__global__ void tp_kernel(const float* __restrict__ o,
                          const float* __restrict__ Mfo,
                          const float* __restrict__ cfo,
                          float* __restrict__ tp) {
    const int row  = (blockIdx.x << 3) + (threadIdx.x >> 5);
    const int lane = threadIdx.x & 31;
    const float4 a4 = *(const float4*)(o + (size_t)row*E_ + (lane << 2));
    const float4 b4 = *(const float4*)(o + (size_t)row*E_ + 128 + (lane << 2));
    float s0 = 0.f, s1 = 0.f;
#pragma unroll
    for (int u = 0; u < 4; u++) {
        int e0 = (lane << 2) + u;
        float a = (u==0)?a4.x:(u==1)?a4.y:(u==2)?a4.z:a4.w;
        float b = (u==0)?b4.x:(u==1)?b4.y:(u==2)?b4.z:b4.w;
        float2 m0 = *(const float2*)&Mfo[e0*2];
        float2 m1 = *(const float2*)&Mfo[(e0+128)*2];
        s0 = fmaf(a, m0.x, fmaf(b, m1.x, s0));
        s1 = fmaf(a, m0.y, fmaf(b, m1.y, s1));
    }
#pragma unroll
    for (int off = 16; off; off >>= 1) {
        s0 += __shfl_xor_sync(0xffffffffu, s0, off);
        s1 += __shfl_xor_sync(0xffffffffu, s1, off);
    }
    if (lane == 0) {
        tp[row*2+0] = tanhf(s0 + cfo[0]);
        tp[row*2+1] = tanhf(s1 + cfo[1]);
    }
}

__global__ void outputs_kernel(const float* __restrict__ x,
                               const float* __restrict__ tp,
                               const float* __restrict__ pos_w,
                               const float* __restrict__ pos_b,
                               float* __restrict__ out) {
    int idx = blockIdx.x * blockDim.x + threadIdx.x;
    if (idx < NPATCH) {
        const int pix = idx % 81;
        const int c   = (idx / 81) % 3;
        const int bp  = idx / 243;
        const int iy  = pix / 9, ix = pix % 9;
        const int b   = bp >> 8;

        const float tx = tp[bp*2], ty = tp[bp*2+1];
        const float bx = (2.f*ix + 1.f) / 9.f - 1.f;
        const float by = (2.f*iy + 1.f) / 9.f - 1.f;
        const float gx = 0.140625f * bx + tx;
        const float gy = 0.140625f * by + ty;
        const float ixf = ((gx + 1.f) * 64.f - 1.f) * 0.5f;
        const float iyf = ((gy + 1.f) * 64.f - 1.f) * 0.5f;
        const float x0 = floorf(ixf), y0 = floorf(iyf);
        const float wx = ixf - x0,   wy = iyf - y0;
        const int x0i = min(max((int)x0, 0), 63);
        const int x1i = min(max((int)x0 + 1, 0), 63);
        const int y0i = min(max((int)y0, 0), 63);
        const int y1i = min(max((int)y0 + 1, 0), 63);
        const float* img = x + (size_t)(b*3 + c) * 4096;
        const float v00 = img[y0i*64 + x0i], v01 = img[y0i*64 + x1i];
        const float v10 = img[y1i*64 + x0i], v11 = img[y1i*64 + x1i];
        out[idx] = v00*(1.f-wx)*(1.f-wy) + v01*wx*(1.f-wy)
                 + v10*(1.f-wx)*wy       + v11*wx*wy;
    } else {
        int j = idx - NPATCH;
        if (j >= NPOS) return;
        const int d = j & 63, bp = j >> 6;
        out[idx] = tp[bp*2] * pos_w[d] + tp[bp*2+1] * pos_w[64 + d] + pos_b[d];
    }
}

// =====================================================================
extern "C" void kernel_launch(void* const* d_in, const int* in_sizes, int n_in,
                              void* d_out, int out_size) {
    const float* x      = (const float*)d_in[0];
    const float* conv_w = (const float*)d_in[1];
    const float* conv_b = (const float*)d_in[2];
    const float* in_w   = (const float*)d_in[3];
    const float* in_b   = (const float*)d_in[4];
    const float* wq     = (const float*)d_in[5];
    const float* bq     = (const float*)d_in[6];
    const float* wk     = (const float*)d_in[7];
    const float* bk     = (const float*)d_in[8];
    const float* wv     = (const float*)d_in[9];
    const float* bv     = (const float*)d_in[10];
    const float* wo     = (const float*)d_in[11];
    const float* bo     = (const float*)d_in[12];
    const float* out_w  = (const float*)d_in[13];
    const float* out_b  = (const float*)d_in[14];
    const float* fc_w   = (const float*)d_in[15];
    const float* fc_b   = (const float*)d_in[16];
    const float* pos_w  = (const float*)d_in[17];
    const float* pos_b  = (const float*)d_in[18];
    float* outp = (float*)d_out;

    __nv_bfloat16 *wH, *wL, *colH, *colL, *featH, *featL;
    __nv_bfloat16 *inwTh, *inwTl, *qkvwTh, *qkvwTl, *tokH, *tokL, *qkvH, *qkvL;
    float *qkvb, *part, *o, *Mf, *cf, *Mfo, *cfo, *tp;
    cudaGetSymbolAddress((void**)&wH,   g_wH);
    cudaGetSymbolAddress((void**)&wL,   g_wL);
    cudaGetSymbolAddress((void**)&colH, g_colH);
    cudaGetSymbolAddress((void**)&colL, g_colL);
    cudaGetSymbolAddress((void**)&featH, g_featH);
    cudaGetSymbolAddress((void**)&featL, g_featL);
    cudaGetSymbolAddress((void**)&inwTh, g_inwTh);
    cudaGetSymbolAddress((void**)&inwTl, g_inwTl);
    cudaGetSymbolAddress((void**)&qkvwTh, g_qkvwTh);
    cudaGetSymbolAddress((void**)&qkvwTl, g_qkvwTl);
    cudaGetSymbolAddress((void**)&qkvb, g_qkvb);
    cudaGetSymbolAddress((void**)&part, g_part);
    cudaGetSymbolAddress((void**)&tokH, g_tokH);
    cudaGetSymbolAddress((void**)&tokL, g_tokL);
    cudaGetSymbolAddress((void**)&qkvH, g_qkvH);
    cudaGetSymbolAddress((void**)&qkvL, g_qkvL);
    cudaGetSymbolAddress((void**)&o,    g_o);
    cudaGetSymbolAddress((void**)&Mf,   g_Mf);
    cudaGetSymbolAddress((void**)&cf,   g_cf);
    cudaGetSymbolAddress((void**)&Mfo,  g_Mfo);
    cudaGetSymbolAddress((void**)&cfo,  g_cfo);
    cudaGetSymbolAddress((void**)&tp,   g_tp);

    cudaFuncSetAttribute(gemm_wmma<1>, cudaFuncAttributeMaxDynamicSharedMemorySize, GEMM_SMEM);
    cudaFuncSetAttribute(gemm_wmma<2>, cudaFuncAttributeMaxDynamicSharedMemorySize, GEMM_SMEM);
    cudaFuncSetAttribute(gemm_wmma<3>, cudaFuncAttributeMaxDynamicSharedMemorySize, GEMM_SMEM);
    cudaFuncSetAttribute(attn_wmma_kernel, cudaFuncAttributeMaxDynamicSharedMemorySize, ATT_SMEM);

    prep_small_kernel<<<516, 256>>>(conv_w, wH, wL, bq, bk, bv, qkvb,
                                    out_w, out_b, fc_w, fc_b, Mf, cf);               // 0
    fold_kernel<<<E_ + 1, 256>>>(wo, bo, Mf, cf, Mfo, cfo, E_, E_);                  // 1
    im2col_kernel<<<(int)(((size_t)B_*HW_*(KC_/4) + 255)/256), 256>>>(x, colH, colL);// 2

    // ---- conv as GEMM (index 3 = ncu profiled; control) ----
    gemm_wmma<2><<<dim3(32, 2, 16), 256, GEMM_SMEM>>>(
        wH, wL, colH, colL, KC_, HW_, KC_,
        (size_t)HW_*KC_, (size_t)E_*HW_, 0,
        conv_b, nullptr, featH, featL);                                              // 3

    transpose_all_kernel<<<dim3(8, 152), dim3(32, 8)>>>(in_w, wq, wk, wv,
                                                        inwTh, inwTl, qkvwTh, qkvwTl); // 4

    // ---- tok = feat @ in_w + in_b (split-K=4) ----
    gemm_wmma<1><<<dim3(2, 32, 4), 256, GEMM_SMEM>>>(
        featH, featL, inwTh, inwTl, HW_, E_, 1024,
        0, (size_t)BP_*E_, 1024,
        nullptr, part, nullptr, nullptr);                                            // 5
    reduce_tok_kernel<<<((BP_*E_)/4 + 255)/256, 256>>>(part, in_b, tokH, tokL);      // 6

    // ---- fused QKV -> bf16 hi/lo ----
    gemm_wmma<3><<<dim3(6, 32, 1), 256, GEMM_SMEM>>>(
        tokH, tokL, qkvwTh, qkvwTl, E_, QKVN, E_,
        0, 0, 0,
        qkvb, nullptr, qkvH, qkvL);                                                  // 7

    // ---- tensor-core attention ----
    attn_wmma_kernel<<<dim3(4, B_*NH_), 256, ATT_SMEM>>>(qkvH, qkvL, o);             // 8

    // ---- tp = tanh(o @ Mfo + cfo) ----
    tp_kernel<<<BP_/8, 256>>>(o, Mfo, cfo, tp);                                      // 9

    // ---- outputs ----
    outputs_kernel<<<(NPATCH + NPOS + 255)/256, 256>>>(x, tp, pos_w, pos_b, outp);   // 10
}

// round 16
// speedup vs baseline: 1.0584x; 1.0152x over previous
#include <cuda_runtime.h>
#include <cuda_bf16.h>
#include <mma.h>
#include <cstdint>
#include <math.h>

using namespace nvcuda;

#define B_    16
#define C_    3
#define H_    64
#define W_    64
#define P_    256
#define PS_   9
#define E_    256
#define NH_   8
#define DH_   32
#define HW_   4096
#define POSD_ 64
#define BP_   (B_*P_)               // 4096
#define NPATCH (B_*P_*C_*PS_*PS_)   // 995328
#define NPOS   (BP_*POSD_)          // 262144
#define QKVN  768
#define KC_   256                   // conv GEMM K (243 padded)

// ---------------- scratch ----------------
__device__ __nv_bfloat16 g_wH [E_*KC_];
__device__ __nv_bfloat16 g_wL [E_*KC_];
__device__ __nv_bfloat16 g_colH[(size_t)B_*HW_*KC_];
__device__ __nv_bfloat16 g_colL[(size_t)B_*HW_*KC_];
__device__ __nv_bfloat16 g_featH[(size_t)BP_*HW_];
__device__ __nv_bfloat16 g_featL[(size_t)BP_*HW_];
__device__ __nv_bfloat16 g_inwTh[(size_t)E_*HW_];
__device__ __nv_bfloat16 g_inwTl[(size_t)E_*HW_];
__device__ __nv_bfloat16 g_qkvwTh[QKVN*E_];
__device__ __nv_bfloat16 g_qkvwTl[QKVN*E_];
__device__ float g_qkvb[QKVN];
__device__ float g_part[4*(size_t)BP_*E_];
__device__ __nv_bfloat16 g_tokH[BP_*E_];
__device__ __nv_bfloat16 g_tokL[BP_*E_];
__device__ __nv_bfloat16 g_qkvH[(size_t)BP_*QKVN];
__device__ __nv_bfloat16 g_qkvL[(size_t)BP_*QKVN];
__device__ float g_o  [BP_*E_];
__device__ float g_Mf [E_*2];
__device__ float g_cf [2];
__device__ float g_Mfo[E_*2];
__device__ float g_cfo[2];
__device__ float g_tp [BP_*2];

// ---------------- cp.async helpers ----------------
__device__ __forceinline__ uint32_t smem_u32(const void* p) {
    uint32_t a;
    asm("{ .reg .u64 t; cvta.to.shared.u64 t, %1; cvt.u32.u64 %0, t; }" : "=r"(a) : "l"(p));
    return a;
}
#define CP_ASYNC16(dst, src) \
    asm volatile("cp.async.cg.shared.global [%0], [%1], 16;" :: "r"(dst), "l"(src))
#define CP_COMMIT() asm volatile("cp.async.commit_group;" ::: "memory")
#define CP_WAIT0()  asm volatile("cp.async.wait_group 0;" ::: "memory")

__device__ __forceinline__ uint2 pack4_bf16(float a, float b, float c, float d) {
    __nv_bfloat162 lo = __floats2bfloat162_rn(a, b);
    __nv_bfloat162 hi = __floats2bfloat162_rn(c, d);
    uint2 r;
    r.x = *(uint32_t*)&lo;
    r.y = *(uint32_t*)&hi;
    return r;
}

// =====================================================================
// prep_small: wprep (0..255) + concat_bias (256..258) + fold1 (259..515)
// =====================================================================
__global__ void prep_small_kernel(const float* __restrict__ conv_w,
                                  __nv_bfloat16* __restrict__ wH,
                                  __nv_bfloat16* __restrict__ wL,
                                  const float* __restrict__ bq,
                                  const float* __restrict__ bk,
                                  const float* __restrict__ bv,
                                  float* __restrict__ qkvb,
                                  const float* __restrict__ out_w,
                                  const float* __restrict__ out_b,
                                  const float* __restrict__ fc_w,
                                  const float* __restrict__ fc_b,
                                  float* __restrict__ Mf,
                                  float* __restrict__ cf) {
    const int bid = blockIdx.x, tid = threadIdx.x;
    if (bid < 256) {
        int idx = bid*256 + tid;
        int oc = idx >> 8, k = idx & 255;
        float v = (k < 243) ? conv_w[oc*243 + k] : 0.f;
        __nv_bfloat16 h = __float2bfloat16(v);
        wH[idx] = h;
        wL[idx] = __float2bfloat16(v - __bfloat162float(h));
        return;
    }
    if (bid < 259) {
        int i = (bid - 256)*256 + tid;
        if (i < 768) qkvb[i] = (i < 256) ? bq[i] : (i < 512 ? bk[i-256] : bv[i-512]);
        return;
    }
    const int e = bid - 259;
    const float* arow = (e < E_) ? (out_w + (size_t)e*HW_) : out_b;
    float s0 = 0.f, s1 = 0.f;
    for (int i = tid; i < HW_; i += 256) {
        float a = arow[i];
        float2 f = *(const float2*)&fc_w[i*2];
        s0 = fmaf(a, f.x, s0);
        s1 = fmaf(a, f.y, s1);
    }
    __shared__ float red0[8], red1[8];
    const int lane = tid & 31, warp = tid >> 5;
#pragma unroll
    for (int o = 16; o; o >>= 1) {
        s0 += __shfl_xor_sync(0xffffffffu, s0, o);
        s1 += __shfl_xor_sync(0xffffffffu, s1, o);
    }
    if (lane == 0) { red0[warp] = s0; red1[warp] = s1; }
    __syncthreads();
    if (tid == 0) {
        float t0 = 0.f, t1 = 0.f;
#pragma unroll
        for (int i = 0; i < 8; i++) { t0 += red0[i]; t1 += red1[i]; }
        if (e < E_) { Mf[e*2] = t0; Mf[e*2+1] = t1; }
        else        { cf[0] = t0 + fc_b[0]; cf[1] = t1 + fc_b[1]; }
    }
}

// =====================================================================
// im2col (vectorized)
// =====================================================================
__global__ void im2col_kernel(const float* __restrict__ x,
                              __nv_bfloat16* __restrict__ colH,
                              __nv_bfloat16* __restrict__ colL) {
    size_t t = (size_t)blockIdx.x*256 + threadIdx.x;
    if (t >= (size_t)B_*HW_*(KC_/4)) return;
    int k4  = (int)(t & 63);
    int pix = (int)((t >> 6) & 4095);
    int b   = (int)(t >> 18);
    const int py = pix >> 6, px = pix & 63;

    float vh[4], vl[4];
#pragma unroll
    for (int u = 0; u < 4; u++) {
        int k = (k4 << 2) + u;
        float v = 0.f;
        if (k < 243) {
            int c  = k / 81;
            int r  = k - c*81;
            int ky = r / 9;
            int kx = r - ky*9;
            int yy = py + ky - 4;
            int xx = px + kx - 4;
            if (yy >= 0 && yy < 64 && xx >= 0 && xx < 64)
                v = x[((size_t)(b*3 + c) << 12) + (yy << 6) + xx];
        }
        float h = __bfloat162float(__float2bfloat16(v));
        vh[u] = v;
        vl[u] = v - h;
    }
    size_t base = ((size_t)b << 20) + ((size_t)pix << 8) + (k4 << 2);
    *(uint2*)(colH + base) = pack4_bf16(vh[0], vh[1], vh[2], vh[3]);
    *(uint2*)(colL + base) = pack4_bf16(vl[0], vl[1], vl[2], vl[3]);
}

// =====================================================================
// Batched transpose + bf16 split
// =====================================================================
__global__ void transpose_all_kernel(const float* __restrict__ in_w,
                                     const float* __restrict__ wq,
                                     const float* __restrict__ wk,
                                     const float* __restrict__ wv,
                                     __nv_bfloat16* __restrict__ inwTh,
                                     __nv_bfloat16* __restrict__ inwTl,
                                     __nv_bfloat16* __restrict__ qkvwTh,
                                     __nv_bfloat16* __restrict__ qkvwTl) {
    __shared__ float tile[32][33];
    const int y = blockIdx.y;
    const float* src; int Kd, k0;
    __nv_bfloat16 *oH, *oL;
    if (y < 128) {
        src = in_w; Kd = HW_; k0 = y << 5; oH = inwTh; oL = inwTl;
    } else {
        int g  = (y - 128) >> 3;
        int yy = (y - 128) & 7;
        src = (g == 0) ? wq : (g == 1) ? wk : wv;
        Kd = E_; k0 = yy << 5;
        oH = qkvwTh + g*256*E_; oL = qkvwTl + g*256*E_;
    }
    const int n0 = blockIdx.x << 5;
    const int tx = threadIdx.x, ty = threadIdx.y;
    for (int i = ty; i < 32; i += 8)
        tile[i][tx] = src[(size_t)(k0 + i)*E_ + n0 + tx];
    __syncthreads();
    for (int i = ty; i < 32; i += 8) {
        float v = tile[tx][i];
        __nv_bfloat16 h = __float2bfloat16(v);
        size_t o = (size_t)(n0 + i)*Kd + k0 + tx;
        oH[o] = h;
        oL[o] = __float2bfloat16(v - __bfloat162float(h));
    }
}

// =====================================================================
// wmma bf16-split GEMM (proven best config).
// =====================================================================
#define LDS_  40
#define TILE_B (128*LDS_*2)
#define STAGE_B (4*TILE_B)
#define GEMM_SMEM (2*STAGE_B)        // 81920 B

template<int MODE>
__global__ __launch_bounds__(256, 2)
void gemm_wmma(const __nv_bfloat16* __restrict__ Ah, const __nv_bfloat16* __restrict__ Al,
               const __nv_bfloat16* __restrict__ Bh, const __nv_bfloat16* __restrict__ Bl,
               int K, int ldc, int kLen, size_t bOffZ, size_t cOffZ, int kOffZ,
               const float* __restrict__ bias, float* __restrict__ C,
               __nv_bfloat16* __restrict__ CH, __nv_bfloat16* __restrict__ CL) {
    extern __shared__ char smem[];
    const int tid = threadIdx.x;
    const int wid = tid >> 5;
    const int warpM = wid & 1;
    const int warpN = wid >> 1;
    const int mBase = blockIdx.y << 7;
    const int nBase = blockIdx.x << 7;
    const int z = blockIdx.z;

    Bh += (size_t)z * bOffZ;  Bl += (size_t)z * bOffZ;
    if (MODE == 2 || MODE == 3) { CH += (size_t)z * cOffZ; CL += (size_t)z * cOffZ; }
    else                          C  += (size_t)z * cOffZ;
    const int k0 = z * kOffZ;

    const __nv_bfloat16* srcs[4] = {
        Ah + (size_t)mBase*K, Al + (size_t)mBase*K,
        Bh + (size_t)nBase*K, Bl + (size_t)nBase*K };

    const uint32_t smemBase = smem_u32(smem);

    auto load_stage = [&](int s, int kg) {
        const uint32_t sb = smemBase + s*STAGE_B;
#pragma unroll
        for (int t = 0; t < 4; t++) {
            const __nv_bfloat16* src = srcs[t];
            const uint32_t dst = sb + t*TILE_B;
#pragma unroll
            for (int i = 0; i < 2; i++) {
                int idx = tid + (i << 8);
                int row = idx >> 2, seg = idx & 3;
                CP_ASYNC16(dst + (uint32_t)(row*(LDS_*2) + seg*16),
                           (const char*)(src + (size_t)row*K + kg + seg*8));
            }
        }
    };

    wmma::fragment<wmma::accumulator, 16,16,16, float> acc[4][2];
#pragma unroll
    for (int i = 0; i < 4; i++)
#pragma unroll
        for (int j = 0; j < 2; j++) wmma::fill_fragment(acc[i][j], 0.f);

    const int nChunks = kLen >> 5;
    load_stage(0, k0); CP_COMMIT();

    for (int c = 0; c < nChunks; c++) {
        CP_WAIT0();
        __syncthreads();
        if (c + 1 < nChunks) { load_stage((c+1) & 1, k0 + ((c+1) << 5)); CP_COMMIT(); }

        const __nv_bfloat16* As_h = (const __nv_bfloat16*)(smem + (c&1)*STAGE_B);
        const __nv_bfloat16* As_l = As_h + 128*LDS_;
        const __nv_bfloat16* Bs_h = As_l + 128*LDS_;
        const __nv_bfloat16* Bs_l = Bs_h + 128*LDS_;

#pragma unroll
        for (int ks = 0; ks < 2; ks++) {
            wmma::fragment<wmma::matrix_a, 16,16,16, __nv_bfloat16, wmma::row_major> a_h[4], a_l[4];
            wmma::fragment<wmma::matrix_b, 16,16,16, __nv_bfloat16, wmma::col_major> b_h[2], b_l[2];
#pragma unroll
            for (int i = 0; i < 4; i++) {
                const int r = (warpM*64 + i*16)*LDS_ + ks*16;
                wmma::load_matrix_sync(a_h[i], As_h + r, LDS_);
                wmma::load_matrix_sync(a_l[i], As_l + r, LDS_);
            }
#pragma unroll
            for (int j = 0; j < 2; j++) {
                const int r = (warpN*32 + j*16)*LDS_ + ks*16;
                wmma::load_matrix_sync(b_h[j], Bs_h + r, LDS_);
                wmma::load_matrix_sync(b_l[j], Bs_l + r, LDS_);
            }
#pragma unroll
            for (int i = 0; i < 4; i++)
#pragma unroll
                for (int j = 0; j < 2; j++) {
                    wmma::mma_sync(acc[i][j], a_h[i], b_h[j], acc[i][j]);
                    wmma::mma_sync(acc[i][j], a_h[i], b_l[j], acc[i][j]);
                    wmma::mma_sync(acc[i][j], a_l[i], b_h[j], acc[i][j]);
                }
        }
    }

    if (MODE == 1) {
#pragma unroll
        for (int i = 0; i < 4; i++)
#pragma unroll
            for (int j = 0; j < 2; j++)
                wmma::store_matrix_sync(
                    C + (size_t)(mBase + warpM*64 + i*16)*ldc + nBase + warpN*32 + j*16,
                    acc[i][j], ldc, wmma::mem_row_major);
        return;
    }

    __syncthreads();
    float* sC = (float*)smem;
#pragma unroll
    for (int i = 0; i < 4; i++)
#pragma unroll
        for (int j = 0; j < 2; j++)
            wmma::store_matrix_sync(sC + (size_t)(warpM*64 + i*16)*128 + warpN*32 + j*16,
                                    acc[i][j], 128, wmma::mem_row_major);
    __syncthreads();

#pragma unroll
    for (int t = 0; t < 16; t++) {
        int lin = tid + (t << 8);
        int row = lin >> 5;
        int col = (lin & 31) << 2;
        float4 v = *(const float4*)(sC + row*128 + col);
        const int gm = mBase + row, gn = nBase + col;
        if (MODE == 3) {
            const float4 bv = *(const float4*)(bias + gn);
            float r0 = v.x + bv.x, r1 = v.y + bv.y, r2 = v.z + bv.z, r3 = v.w + bv.w;
            float h0 = __bfloat162float(__float2bfloat16(r0));
            float h1 = __bfloat162float(__float2bfloat16(r1));
            float h2 = __bfloat162float(__float2bfloat16(r2));
            float h3 = __bfloat162float(__float2bfloat16(r3));
            *(uint2*)(CH + (size_t)gm*ldc + gn) = pack4_bf16(r0, r1, r2, r3);
            *(uint2*)(CL + (size_t)gm*ldc + gn) =
                pack4_bf16(r0 - h0, r1 - h1, r2 - h2, r3 - h3);
        } else {
            const float bb = bias[gm];
            float r0 = fmaxf(v.x + bb, 0.f), r1 = fmaxf(v.y + bb, 0.f);
            float r2 = fmaxf(v.z + bb, 0.f), r3 = fmaxf(v.w + bb, 0.f);
            float h0 = __bfloat162float(__float2bfloat16(r0));
            float h1 = __bfloat162float(__float2bfloat16(r1));
            float h2 = __bfloat162float(__float2bfloat16(r2));
            float h3 = __bfloat162float(__float2bfloat16(r3));
            *(uint2*)(CH + (size_t)gm*ldc + gn) = pack4_bf16(r0, r1, r2, r3);
            *(uint2*)(CL + (size_t)gm*ldc + gn) =
                pack4_bf16(r0 - h0, r1 - h1, r2 - h2, r3 - h3);
        }
    }
}

// reduce split-K partials + bias -> tok bf16 hi/lo (vectorized x4)
__global__ void reduce_tok_kernel(const float* __restrict__ part,
                                  const float* __restrict__ bias,
                                  __nv_bfloat16* __restrict__ tokH,
                                  __nv_bfloat16* __restrict__ tokL) {
    int t = blockIdx.x*256 + threadIdx.x;
    if (t >= (BP_*E_)/4) return;
    const int idx = t << 2;
    const size_t S = (size_t)BP_*E_;
    float4 p0 = *(const float4*)(part + idx);
    float4 p1 = *(const float4*)(part + idx + S);
    float4 p2 = *(const float4*)(part + idx + 2*S);
    float4 p3 = *(const float4*)(part + idx + 3*S);
    float4 bv = *(const float4*)(bias + (idx & 255));
    float v0 = p0.x + p1.x + p2.x + p3.x + bv.x;
    float v1 = p0.y + p1.y + p2.y + p3.y + bv.y;
    float v2 = p0.z + p1.z + p2.z + p3.z + bv.z;
    float v3 = p0.w + p1.w + p2.w + p3.w + bv.w;
    float h0 = __bfloat162float(__float2bfloat16(v0));
    float h1 = __bfloat162float(__float2bfloat16(v1));
    float h2 = __bfloat162float(__float2bfloat16(v2));
    float h3 = __bfloat162float(__float2bfloat16(v3));
    *(uint2*)(tokH + idx) = pack4_bf16(v0, v1, v2, v3);
    *(uint2*)(tokL + idx) = pack4_bf16(v0 - h0, v1 - h1, v2 - h2, v3 - h3);
}

// =====================================================================
// Tensor-core attention (R12 proven)
// =====================================================================
#define ASLD 264
#define ATT_SMEM (64*ASLD*4 + 2*(64*ASLD*2) + 2*(64*40*2) + 4*(256*40*2))  // 227328 B

__global__ __launch_bounds__(256)
void attn_wmma_kernel(const __nv_bfloat16* __restrict__ qkvH,
                      const __nv_bfloat16* __restrict__ qkvL,
                      float* __restrict__ o) {
    extern __shared__ char sm_[];
    float*        sS  = (float*)sm_;
    __nv_bfloat16* sPh = (__nv_bfloat16*)(sS + 64*ASLD);
    __nv_bfloat16* sPl = sPh + 64*ASLD;
    __nv_bfloat16* sQh = sPl + 64*ASLD;
    __nv_bfloat16* sQl = sQh + 64*40;
    __nv_bfloat16* sKh = sQl + 64*40;
    __nv_bfloat16* sKl = sKh + 256*40;
    __nv_bfloat16* sVh = sKl + 256*40;
    __nv_bfloat16* sVl = sVh + 256*40;

    const int bh = blockIdx.y, b = bh >> 3, h = bh & 7;
    const int q0 = blockIdx.x << 6;
    const int tid = threadIdx.x;
    const int wid = tid >> 5;
    const float scale = 0.17677669529663687f;

    const size_t rowQ = (size_t)(b*P_ + q0)*QKVN + h*32;
    const size_t rowK = (size_t)(b*P_)*QKVN + 256 + h*32;
    const size_t rowV = (size_t)(b*P_)*QKVN + 512 + h*32;
    for (int i = tid; i < 512; i += 256) {
        int a = i >> 8, r = (i >> 2) & 63, s = i & 3;
        const __nv_bfloat16* src = (a ? qkvL : qkvH) + rowQ + (size_t)r*QKVN + s*8;
        *(uint4*)((a ? sQl : sQh) + r*40 + s*8) = *(const uint4*)src;
    }
    for (int i = tid; i < 2048; i += 256) {
        int a = i >> 10, r = (i >> 2) & 255, s = i & 3;
        const __nv_bfloat16* srck = (a ? qkvL : qkvH) + rowK + (size_t)r*QKVN + s*8;
        *(uint4*)((a ? sKl : sKh) + r*40 + s*8) = *(const uint4*)srck;
        const __nv_bfloat16* srcv = (a ? qkvL : qkvH) + rowV + (size_t)r*QKVN + s*8;
        *(uint4*)((a ? sVl : sVh) + r*40 + s*8) = *(const uint4*)srcv;
    }
    __syncthreads();

    {
        const int wm = wid & 1, wn = wid >> 1;
        wmma::fragment<wmma::accumulator, 16,16,16, float> acc[2][4];
#pragma unroll
        for (int i = 0; i < 2; i++)
#pragma unroll
            for (int j = 0; j < 4; j++) wmma::fill_fragment(acc[i][j], 0.f);
#pragma unroll
        for (int ks = 0; ks < 2; ks++) {
            wmma::fragment<wmma::matrix_a, 16,16,16, __nv_bfloat16, wmma::row_major> a_h[2], a_l[2];
            wmma::fragment<wmma::matrix_b, 16,16,16, __nv_bfloat16, wmma::col_major> b_h[4], b_l[4];
#pragma unroll
            for (int i = 0; i < 2; i++) {
                const int r = (wm*32 + i*16)*40 + ks*16;
                wmma::load_matrix_sync(a_h[i], sQh + r, 40);
                wmma::load_matrix_sync(a_l[i], sQl + r, 40);
            }
#pragma unroll
            for (int j = 0; j < 4; j++) {
                const int r = (wn*64 + j*16)*40 + ks*16;
                wmma::load_matrix_sync(b_h[j], sKh + r, 40);
                wmma::load_matrix_sync(b_l[j], sKl + r, 40);
            }
#pragma unroll
            for (int i = 0; i < 2; i++)
#pragma unroll
                for (int j = 0; j < 4; j++) {
                    wmma::mma_sync(acc[i][j], a_h[i], b_h[j], acc[i][j]);
                    wmma::mma_sync(acc[i][j], a_h[i], b_l[j], acc[i][j]);
                    wmma::mma_sync(acc[i][j], a_l[i], b_h[j], acc[i][j]);
                }
        }
#pragma unroll
        for (int i = 0; i < 2; i++)
#pragma unroll
            for (int j = 0; j < 4; j++)
                wmma::store_matrix_sync(sS + (wm*32 + i*16)*ASLD + wn*64 + j*16,
                                        acc[i][j], ASLD, wmma::mem_row_major);
    }
    __syncthreads();

    {
        const int warp = wid, lane = tid & 31;
        for (int r = warp; r < 64; r += 8) {
            float4* row = (float4*)(sS + r*ASLD);
            float4 v0 = row[lane], v1 = row[lane + 32];
            v0.x *= scale; v0.y *= scale; v0.z *= scale; v0.w *= scale;
            v1.x *= scale; v1.y *= scale; v1.z *= scale; v1.w *= scale;
            float m = fmaxf(fmaxf(fmaxf(v0.x,v0.y), fmaxf(v0.z,v0.w)),
                            fmaxf(fmaxf(v1.x,v1.y), fmaxf(v1.z,v1.w)));
#pragma unroll
            for (int off = 16; off; off >>= 1) m = fmaxf(m, __shfl_xor_sync(0xffffffffu, m, off));
            v0.x = __expf(v0.x-m); v0.y = __expf(v0.y-m); v0.z = __expf(v0.z-m); v0.w = __expf(v0.w-m);
            v1.x = __expf(v1.x-m); v1.y = __expf(v1.y-m); v1.z = __expf(v1.z-m); v1.w = __expf(v1.w-m);
            float s = v0.x+v0.y+v0.z+v0.w + v1.x+v1.y+v1.z+v1.w;
#pragma unroll
            for (int off = 16; off; off >>= 1) s += __shfl_xor_sync(0xffffffffu, s, off);
            const float inv = 1.f / s;
            v0.x*=inv; v0.y*=inv; v0.z*=inv; v0.w*=inv;
            v1.x*=inv; v1.y*=inv; v1.z*=inv; v1.w*=inv;
            row[lane] = v0; row[lane+32] = v1;
        }
    }
    __syncthreads();

    for (int i = tid; i < 4096; i += 256) {
        int r = i >> 6, g = (i & 63) << 2;
        float4 v = *(const float4*)(sS + r*ASLD + g);
        float h0 = __bfloat162float(__float2bfloat16(v.x));
        float h1 = __bfloat162float(__float2bfloat16(v.y));
        float h2 = __bfloat162float(__float2bfloat16(v.z));
        float h3 = __bfloat162float(__float2bfloat16(v.w));
        *(uint2*)(sPh + r*ASLD + g) = pack4_bf16(v.x, v.y, v.z, v.w);
        *(uint2*)(sPl + r*ASLD + g) = pack4_bf16(v.x - h0, v.y - h1, v.z - h2, v.w - h3);
    }
    __syncthreads();

    {
        const int wm = wid & 3, wn = wid >> 2;
        wmma::fragment<wmma::accumulator, 16,16,16, float> acc;
        wmma::fill_fragment(acc, 0.f);
#pragma unroll
        for (int k = 0; k < 16; k++) {
            wmma::fragment<wmma::matrix_a, 16,16,16, __nv_bfloat16, wmma::row_major> a_h, a_l;
            wmma::fragment<wmma::matrix_b, 16,16,16, __nv_bfloat16, wmma::row_major> b_h, b_l;
            wmma::load_matrix_sync(a_h, sPh + (wm*16)*ASLD + k*16, ASLD);
            wmma::load_matrix_sync(a_l, sPl + (wm*16)*ASLD + k*16, ASLD);
            wmma::load_matrix_sync(b_h, sVh + (k*16)*40 + wn*16, 40);
            wmma::load_matrix_sync(b_l, sVl + (k*16)*40 + wn*16, 40);
            wmma::mma_sync(acc, a_h, b_h, acc);
            wmma::mma_sync(acc, a_h, b_l, acc);
            wmma::mma_sync(acc, a_l, b_h, acc);
        }
        wmma::store_matrix_sync(o + (size_t)(b*P_ + q0 + wm*16)*E_ + h*32 + wn*16,
                                acc, E_, wmma::mem_row_major);
    }
}

// =====================================================================
// fold2 + tail
// =====================================================================
__global__ void fold_kernel(const float* __restrict__ Wm,
                            const float* __restrict__ brow,
                            const float* __restrict__ M2,
                            const float* __restrict__ addc,
                            float* __restrict__ outM,
                            float* __restrict__ outc, int L, int R) {
    const int e = blockIdx.x, tid = threadIdx.x;
    const float* arow = (e < R) ? (Wm + (size_t)e*L) : brow;
    float s0 = 0.f, s1 = 0.f;
    for (int i = tid; i < L; i += 256) {
        float a = arow[i];
        float2 f = *(const float2*)&M2[i*2];
        s0 = fmaf(a, f.x, s0);
        s1 = fmaf(a, f.y, s1);
    }
    __shared__ float red0[8], red1[8];
    const int lane = tid & 31, warp = tid >> 5;
#pragma unroll
    for (int o = 16; o; o >>= 1) {
        s0 += __shfl_xor_sync(0xffffffffu, s0, o);
        s1 += __shfl_xor_sync(0xffffffffu, s1, o);
    }
    if (lane == 0) { red0[warp] = s0; red1[warp] = s1; }
    __syncthreads();
    if (tid == 0) {
        float t0 = 0.f, t1 = 0.f;
#pragma unroll
        for (int i = 0; i < 8; i++) { t0 += red0[i]; t1 += red1[i]; }
        if (e < R) { outM[e*2] = t0; outM[e*2+1] = t1; }
        else {
            float c0 = addc ? addc[0] : 0.f, c1 = addc ? addc[1] : 0.f;
            outc[0] = t0 + c0; outc[1] = t1 + c1;
        }
    }
}

// tp = tanh(o @ Mfo + cfo); warp per row, float4 loads
__global__ void tp_kernel(const float* __restrict__ o,
                          const float* __restrict__ Mfo,
                          const float* __restrict__ cfo,
                          float* __restrict__ tp) {
    const int row  = (blockIdx.x << 3) + (threadIdx.x >> 5);
    const int lane = threadIdx.x & 31;
    const float4 a4 = *(const float4*)(o + (size_t)row*E_ + (lane << 2));
    const float4 b4 = *(const float4*)(o + (size_t)row*E_ + 128 + (lane << 2));
    float s0 = 0.f, s1 = 0.f;
#pragma unroll
    for (int u = 0; u < 4; u++) {
        int e0 = (lane << 2) + u;
        float a = (u==0)?a4.x:(u==1)?a4.y:(u==2)?a4.z:a4.w;
        float b = (u==0)?b4.x:(u==1)?b4.y:(u==2)?b4.z:b4.w;
        float2 m0 = *(const float2*)&Mfo[e0*2];
        float2 m1 = *(const float2*)&Mfo[(e0+128)*2];
        s0 = fmaf(a, m0.x, fmaf(b, m1.x, s0));
        s1 = fmaf(a, m0.y, fmaf(b, m1.y, s1));
    }
#pragma unroll
    for (int off = 16; off; off >>= 1) {
        s0 += __shfl_xor_sync(0xffffffffu, s0, off);
        s1 += __shfl_xor_sync(0xffffffffu, s1, off);
    }
    if (lane == 0) {
        tp[row*2+0] = tanhf(s0 + cfo[0]);
        tp[row*2+1] = tanhf(s1 + cfo[1]);
    }
}

__global__ void outputs_kernel(const float* __restrict__ x,
                               const float* __restrict__ tp,
                               const float* __restrict__ pos_w,
                               const float* __restrict__ pos_b,
                               float* __restrict__ out) {
    int idx = blockIdx.x * blockDim.x + threadIdx.x;
    if (idx < NPATCH) {
        const int pix = idx % 81;
        const int c   = (idx / 81) % 3;
        const int bp  = idx / 243;
        const int iy  = pix / 9, ix = pix % 9;
        const int b   = bp >> 8;

        const float tx = tp[bp*2], ty = tp[bp*2+1];
        const float bx = (2.f*ix + 1.f) / 9.f - 1.f;
        const float by = (2.f*iy + 1.f) / 9.f - 1.f;
        const float gx = 0.140625f * bx + tx;
        const float gy = 0.140625f * by + ty;
        const float ixf = ((gx + 1.f) * 64.f - 1.f) * 0.5f;
        const float iyf = ((gy + 1.f) * 64.f - 1.f) * 0.5f;
        const float x0 = floorf(ixf), y0 = floorf(iyf);
        const float wx = ixf - x0,   wy = iyf - y0;
        const int x0i = min(max((int)x0, 0), 63);
        const int x1i = min(max((int)x0 + 1, 0), 63);
        const int y0i = min(max((int)y0, 0), 63);
        const int y1i = min(max((int)y0 + 1, 0), 63);
        const float* img = x + (size_t)(b*3 + c) * 4096;
        const float v00 = img[y0i*64 + x0i], v01 = img[y0i*64 + x1i];
        const float v10 = img[y1i*64 + x0i], v11 = img[y1i*64 + x1i];
        out[idx] = v00*(1.f-wx)*(1.f-wy) + v01*wx*(1.f-wy)
                 + v10*(1.f-wx)*wy       + v11*wx*wy;
    } else {
        int j = idx - NPATCH;
        if (j >= NPOS) return;
        const int d = j & 63, bp = j >> 6;
        out[idx] = tp[bp*2] * pos_w[d] + tp[bp*2+1] * pos_w[64 + d] + pos_b[d];
    }
}

// =====================================================================
extern "C" void kernel_launch(void* const* d_in, const int* in_sizes, int n_in,
                              void* d_out, int out_size) {
    const float* x      = (const float*)d_in[0];
    const float* conv_w = (const float*)d_in[1];
    const float* conv_b = (const float*)d_in[2];
    const float* in_w   = (const float*)d_in[3];
    const float* in_b   = (const float*)d_in[4];
    const float* wq     = (const float*)d_in[5];
    const float* bq     = (const float*)d_in[6];
    const float* wk     = (const float*)d_in[7];
    const float* bk     = (const float*)d_in[8];
    const float* wv     = (const float*)d_in[9];
    const float* bv     = (const float*)d_in[10];
    const float* wo     = (const float*)d_in[11];
    const float* bo     = (const float*)d_in[12];
    const float* out_w  = (const float*)d_in[13];
    const float* out_b  = (const float*)d_in[14];
    const float* fc_w   = (const float*)d_in[15];
    const float* fc_b   = (const float*)d_in[16];
    const float* pos_w  = (const float*)d_in[17];
    const float* pos_b  = (const float*)d_in[18];
    float* outp = (float*)d_out;

    __nv_bfloat16 *wH, *wL, *colH, *colL, *featH, *featL;
    __nv_bfloat16 *inwTh, *inwTl, *qkvwTh, *qkvwTl, *tokH, *tokL, *qkvH, *qkvL;
    float *qkvb, *part, *o, *Mf, *cf, *Mfo, *cfo, *tp;
    cudaGetSymbolAddress((void**)&wH,   g_wH);
    cudaGetSymbolAddress((void**)&wL,   g_wL);
    cudaGetSymbolAddress((void**)&colH, g_colH);
    cudaGetSymbolAddress((void**)&colL, g_colL);
    cudaGetSymbolAddress((void**)&featH, g_featH);
    cudaGetSymbolAddress((void**)&featL, g_featL);
    cudaGetSymbolAddress((void**)&inwTh, g_inwTh);
    cudaGetSymbolAddress((void**)&inwTl, g_inwTl);
    cudaGetSymbolAddress((void**)&qkvwTh, g_qkvwTh);
    cudaGetSymbolAddress((void**)&qkvwTl, g_qkvwTl);
    cudaGetSymbolAddress((void**)&qkvb, g_qkvb);
    cudaGetSymbolAddress((void**)&part, g_part);
    cudaGetSymbolAddress((void**)&tokH, g_tokH);
    cudaGetSymbolAddress((void**)&tokL, g_tokL);
    cudaGetSymbolAddress((void**)&qkvH, g_qkvH);
    cudaGetSymbolAddress((void**)&qkvL, g_qkvL);
    cudaGetSymbolAddress((void**)&o,    g_o);
    cudaGetSymbolAddress((void**)&Mf,   g_Mf);
    cudaGetSymbolAddress((void**)&cf,   g_cf);
    cudaGetSymbolAddress((void**)&Mfo,  g_Mfo);
    cudaGetSymbolAddress((void**)&cfo,  g_cfo);
    cudaGetSymbolAddress((void**)&tp,   g_tp);

    cudaFuncSetAttribute(gemm_wmma<1>, cudaFuncAttributeMaxDynamicSharedMemorySize, GEMM_SMEM);
    cudaFuncSetAttribute(gemm_wmma<2>, cudaFuncAttributeMaxDynamicSharedMemorySize, GEMM_SMEM);
    cudaFuncSetAttribute(gemm_wmma<3>, cudaFuncAttributeMaxDynamicSharedMemorySize, GEMM_SMEM);
    cudaFuncSetAttribute(attn_wmma_kernel, cudaFuncAttributeMaxDynamicSharedMemorySize, ATT_SMEM);

    // ---- stream fork for independent prep work (graph-capture-legal) ----
    cudaStream_t s1;
    cudaStreamCreateWithFlags(&s1, cudaStreamNonBlocking);
    cudaEvent_t evF, evI, evP, evJ;
    cudaEventCreateWithFlags(&evF, cudaEventDisableTiming);
    cudaEventCreateWithFlags(&evI, cudaEventDisableTiming);
    cudaEventCreateWithFlags(&evP, cudaEventDisableTiming);
    cudaEventCreateWithFlags(&evJ, cudaEventDisableTiming);

    // fork: s1 branches off the (captured) default stream
    cudaEventRecord(evF, 0);
    cudaStreamWaitEvent(s1, evF, 0);

    // s1: im2col (independent of prep) -> evI; transpose; fold2 (needs Mf via evP) -> evJ
    im2col_kernel<<<(int)(((size_t)B_*HW_*(KC_/4) + 255)/256), 256, 0, s1>>>(x, colH, colL);
    cudaEventRecord(evI, s1);
    transpose_all_kernel<<<dim3(8, 152), dim3(32, 8), 0, s1>>>(in_w, wq, wk, wv,
                                                               inwTh, inwTl, qkvwTh, qkvwTl);

    // s0: prep (wH/wL, qkvb, Mf/cf)
    prep_small_kernel<<<516, 256>>>(conv_w, wH, wL, bq, bk, bv, qkvb,
                                    out_w, out_b, fc_w, fc_b, Mf, cf);
    cudaEventRecord(evP, 0);

    // s1: fold2 after Mf ready
    cudaStreamWaitEvent(s1, evP, 0);
    fold_kernel<<<E_ + 1, 256, 0, s1>>>(wo, bo, Mf, cf, Mfo, cfo, E_, E_);
    cudaEventRecord(evJ, s1);

    // s0: conv GEMM (needs wH from prep [same stream] + col from s1 via evI)
    cudaStreamWaitEvent(0, evI, 0);
    gemm_wmma<2><<<dim3(32, 2, 16), 256, GEMM_SMEM>>>(
        wH, wL, colH, colL, KC_, HW_, KC_,
        (size_t)HW_*KC_, (size_t)E_*HW_, 0,
        conv_b, nullptr, featH, featL);

    // join before tok (needs inwT from s1; Mfo also done by then)
    cudaStreamWaitEvent(0, evJ, 0);

    // ---- tok = feat @ in_w + in_b (split-K=4) ----
    gemm_wmma<1><<<dim3(2, 32, 4), 256, GEMM_SMEM>>>(
        featH, featL, inwTh, inwTl, HW_, E_, 1024,
        0, (size_t)BP_*E_, 1024,
        nullptr, part, nullptr, nullptr);
    reduce_tok_kernel<<<((BP_*E_)/4 + 255)/256, 256>>>(part, in_b, tokH, tokL);

    // ---- fused QKV -> bf16 hi/lo ----
    gemm_wmma<3><<<dim3(6, 32, 1), 256, GEMM_SMEM>>>(
        tokH, tokL, qkvwTh, qkvwTl, E_, QKVN, E_,
        0, 0, 0,
        qkvb, nullptr, qkvH, qkvL);

    // ---- tensor-core attention ----
    attn_wmma_kernel<<<dim3(4, B_*NH_), 256, ATT_SMEM>>>(qkvH, qkvL, o);

    // ---- tp = tanh(o @ Mfo + cfo) ----
    tp_kernel<<<BP_/8, 256>>>(o, Mfo, cfo, tp);

    // ---- outputs ----
    outputs_kernel<<<(NPATCH + NPOS + 255)/256, 256>>>(x, tp, pos_w, pos_b, outp);
}